// round 14
// baseline (speedup 1.0000x reference)
#include <cuda_runtime.h>
#include <cuda_bf16.h>

#define NN 50000
#define EE 500000
#define HH 2
#define GG 128

// ---------------- scratch ----------------
__device__ float d_h1[NN * 128];
__device__ float d_y1[NN * 128];
__device__ float d_h2[NN * 256];
__device__ float d_y2[NN * 256];
__device__ float d_es1[NN * 2], d_ed1[NN * 2];
__device__ float d_es2[NN * 2], d_ed2[NN * 2];
__device__ int   d_deg[NN], d_off[NN + 1], d_cursor[NN];
__device__ int   d_csrc[EE + NN];
__device__ int   d_gstart[GG + 1];
__device__ float d_bs1[128], d_bq1[128];
__device__ float d_bs2[256], d_bq2[256];
__device__ float d_pooled[GG * 256];
__device__ float d_z1[GG * 512], d_z1n[GG * 512];
__device__ float d_z2[GG * 256], d_z2n[GG * 256];

static const int GEMM1_BLOCKS = 2 * ((NN + 127) / 128);            // 782
static const int CSR_BLOCKS = (EE + NN + 255) / 256;               // 2149

// ---------------- CSR: degree count ----------------
__global__ void count_deg(const int* __restrict__ dst, int* __restrict__ deg) {
    int e = blockIdx.x * blockDim.x + threadIdx.x;
    if (e < EE) atomicAdd(&deg[dst[e]], 1);
}

// single-block scan; degree = deg[i] + 1 (implicit self-loop)
__global__ void scan_offsets(const int* __restrict__ deg, int* __restrict__ off,
                             int* __restrict__ cursor) {
    __shared__ int part[1024];
    const int CH = (NN + 1023) / 1024;
    int t = threadIdx.x;
    int base = t * CH;
    int s = 0;
    for (int i = 0; i < CH; i++) {
        int idx = base + i;
        if (idx < NN) s += deg[idx] + 1;
    }
    part[t] = s;
    __syncthreads();
    for (int d = 1; d < 1024; d <<= 1) {
        int v = (t >= d) ? part[t - d] : 0;
        __syncthreads();
        part[t] += v;
        __syncthreads();
    }
    int run = (t == 0) ? 0 : part[t - 1];
    for (int i = 0; i < CH; i++) {
        int idx = base + i;
        if (idx < NN) {
            off[idx] = run;
            cursor[idx] = run;
            run += deg[idx] + 1;
        }
    }
    if (t == 1023) off[NN] = part[1023];
}

// ---------------- tf32 GEMM body ----------------
__device__ __forceinline__ unsigned f2tf(float f) {
    unsigned r;
    asm("cvt.rna.tf32.f32 %0, %1;" : "=r"(r) : "f"(f));
    return r;
}
__device__ __forceinline__ void mma_tf32(float4& c, const unsigned* a, const unsigned* b) {
    asm volatile(
        "mma.sync.aligned.m16n8k8.row.col.f32.tf32.tf32.f32 "
        "{%0,%1,%2,%3}, {%4,%5,%6,%7}, {%8,%9}, {%0,%1,%2,%3};"
        : "+f"(c.x), "+f"(c.y), "+f"(c.z), "+f"(c.w)
        : "r"(a[0]), "r"(a[1]), "r"(a[2]), "r"(a[3]), "r"(b[0]), "r"(b[1]));
}

template <bool APPLY_BN>
__device__ void gemm_body(int bx, int by,
                          const float* __restrict__ A, const float* __restrict__ B,
                          float* __restrict__ C, int M, int N, int K,
                          const float* __restrict__ bs, const float* __restrict__ bq,
                          const float* __restrict__ gamma, const float* __restrict__ beta,
                          const float* __restrict__ asrc, const float* __restrict__ adst,
                          float* __restrict__ es, float* __restrict__ ed) {
    __shared__ unsigned As[128][17];
    __shared__ unsigned Bs[16][72];
    __shared__ float sscale[128], sshift[128];
    const int brow = by * 128;
    const int bcol = bx * 64;
    const int tid = threadIdx.x;
    const int w = tid >> 5, l = tid & 31;
    const int wm = w & 3, wn = w >> 2;
    const int mbase = wm * 32, nbase = wn * 32;
    const int g = l >> 2, tg = l & 3;

    if (APPLY_BN) {
        if (tid < K) {
            float m = bs[tid] / (float)NN;
            float var = bq[tid] / (float)NN - m * m;
            float sc = rsqrtf(var + 1e-5f) * gamma[tid];
            sscale[tid] = sc;
            sshift[tid] = beta[tid] - m * sc;
        }
        __syncthreads();
    }

    float4 acc[2][4];
    #pragma unroll
    for (int i = 0; i < 2; i++)
        #pragma unroll
        for (int j = 0; j < 4; j++) acc[i][j] = make_float4(0.f, 0.f, 0.f, 0.f);

    for (int k0 = 0; k0 < K; k0 += 16) {
        #pragma unroll
        for (int i = tid; i < 512; i += 256) {
            int r = i >> 2, c4 = (i & 3) * 4;
            int gr = brow + r;
            float4 v = make_float4(0.f, 0.f, 0.f, 0.f);
            if (gr < M) {
                v = *(const float4*)(A + (long)gr * K + k0 + c4);
                if (APPLY_BN) {
                    int c = k0 + c4;
                    v.x = fmaxf(fmaf(v.x, sscale[c + 0], sshift[c + 0]), 0.f);
                    v.y = fmaxf(fmaf(v.y, sscale[c + 1], sshift[c + 1]), 0.f);
                    v.z = fmaxf(fmaf(v.z, sscale[c + 2], sshift[c + 2]), 0.f);
                    v.w = fmaxf(fmaf(v.w, sscale[c + 3], sshift[c + 3]), 0.f);
                }
            }
            As[r][c4 + 0] = f2tf(v.x);
            As[r][c4 + 1] = f2tf(v.y);
            As[r][c4 + 2] = f2tf(v.z);
            As[r][c4 + 3] = f2tf(v.w);
        }
        {
            int r = tid >> 4, c4 = (tid & 15) * 4;
            float4 v = *(const float4*)(B + (long)(k0 + r) * N + bcol + c4);
            Bs[r][c4 + 0] = f2tf(v.x);
            Bs[r][c4 + 1] = f2tf(v.y);
            Bs[r][c4 + 2] = f2tf(v.z);
            Bs[r][c4 + 3] = f2tf(v.w);
        }
        __syncthreads();
        #pragma unroll
        for (int k8 = 0; k8 < 16; k8 += 8) {
            unsigned af[2][4], bf[4][2];
            #pragma unroll
            for (int mt = 0; mt < 2; mt++) {
                int r0 = mbase + mt * 16 + g;
                int c = k8 + tg;
                af[mt][0] = As[r0][c];
                af[mt][1] = As[r0 + 8][c];
                af[mt][2] = As[r0][c + 4];
                af[mt][3] = As[r0 + 8][c + 4];
            }
            #pragma unroll
            for (int nt = 0; nt < 4; nt++) {
                int cb = nbase + nt * 8 + g;
                int rb = k8 + tg;
                bf[nt][0] = Bs[rb][cb];
                bf[nt][1] = Bs[rb + 4][cb];
            }
            #pragma unroll
            for (int mt = 0; mt < 2; mt++)
                #pragma unroll
                for (int nt = 0; nt < 4; nt++) mma_tf32(acc[mt][nt], af[mt], bf[nt]);
        }
        __syncthreads();
    }

    #pragma unroll
    for (int mt = 0; mt < 2; mt++) {
        #pragma unroll
        for (int nt = 0; nt < 4; nt++) {
            int row = brow + mbase + mt * 16 + g;
            int col = bcol + nbase + nt * 8 + 2 * tg;
            if (row < M)
                *(float2*)(C + (long)row * N + col) = make_float2(acc[mt][nt].x, acc[mt][nt].y);
            if (row + 8 < M)
                *(float2*)(C + (long)(row + 8) * N + col) = make_float2(acc[mt][nt].z, acc[mt][nt].w);
        }
    }

    // fused attention-logit epilogue
    {
        int head = (2 * bcol >= N) ? 1 : 0;
        float av_s[8], av_d[8];
        #pragma unroll
        for (int nt = 0; nt < 4; nt++) {
            int col = bcol + nbase + nt * 8 + 2 * tg;
            av_s[nt * 2 + 0] = __ldg(asrc + col);
            av_s[nt * 2 + 1] = __ldg(asrc + col + 1);
            av_d[nt * 2 + 0] = __ldg(adst + col);
            av_d[nt * 2 + 1] = __ldg(adst + col + 1);
        }
        #pragma unroll
        for (int mt = 0; mt < 2; mt++) {
            float pes0 = 0.f, ped0 = 0.f, pes8 = 0.f, ped8 = 0.f;
            #pragma unroll
            for (int nt = 0; nt < 4; nt++) {
                float4 a = acc[mt][nt];
                pes0 += a.x * av_s[nt * 2] + a.y * av_s[nt * 2 + 1];
                ped0 += a.x * av_d[nt * 2] + a.y * av_d[nt * 2 + 1];
                pes8 += a.z * av_s[nt * 2] + a.w * av_s[nt * 2 + 1];
                ped8 += a.z * av_d[nt * 2] + a.w * av_d[nt * 2 + 1];
            }
            #pragma unroll
            for (int o = 1; o <= 2; o <<= 1) {
                pes0 += __shfl_xor_sync(0xffffffffu, pes0, o);
                ped0 += __shfl_xor_sync(0xffffffffu, ped0, o);
                pes8 += __shfl_xor_sync(0xffffffffu, pes8, o);
                ped8 += __shfl_xor_sync(0xffffffffu, ped8, o);
            }
            if (tg == 0) {
                int row = brow + mbase + mt * 16 + g;
                if (row < M) {
                    atomicAdd(&es[row * 2 + head], pes0);
                    atomicAdd(&ed[row * 2 + head], ped0);
                }
                if (row + 8 < M) {
                    atomicAdd(&es[(row + 8) * 2 + head], pes8);
                    atomicAdd(&ed[(row + 8) * 2 + head], ped8);
                }
            }
        }
    }
}

// ---------------- combo: gemm1 tiles + CSR fill + graph bounds ----------------
__global__ void combo1(const float* __restrict__ x, const float* __restrict__ W1,
                       float* __restrict__ h1,
                       const float* __restrict__ a_s1, const float* __restrict__ a_d1,
                       float* __restrict__ es1, float* __restrict__ ed1,
                       const int* __restrict__ esrc, const int* __restrict__ edst,
                       int* __restrict__ cursor, int* __restrict__ csrc,
                       const int* __restrict__ batch, int* __restrict__ gstart) {
    int bid = blockIdx.x;
    if (bid < GEMM1_BLOCKS) {
        gemm_body<false>(bid & 1, bid >> 1, x, W1, h1, NN, 128, 64,
                         nullptr, nullptr, nullptr, nullptr, a_s1, a_d1, es1, ed1);
    } else if (bid < GEMM1_BLOCKS + CSR_BLOCKS) {
        int idx = (bid - GEMM1_BLOCKS) * 256 + threadIdx.x;
        if (idx < EE) {
            int t = edst[idx];
            int p = atomicAdd(&cursor[t], 1);
            csrc[p] = esrc[idx];
        } else if (idx < EE + NN) {
            int n = idx - EE;
            int p = atomicAdd(&cursor[n], 1);
            csrc[p] = n;
        }
    } else {
        int g = threadIdx.x;
        if (g <= GG) {
            int lo = 0, hi = NN;
            while (lo < hi) {
                int mid = (lo + hi) >> 1;
                if (batch[mid] < g) lo = mid + 1; else hi = mid;
            }
            gstart[g] = lo;
        }
    }
}

__global__ void gemm_k(int nbx, const float* A, const float* B, float* C, int M, int N, int K,
                       const float* bs, const float* bq, const float* gamma, const float* beta,
                       const float* asrc, const float* adst, float* es, float* ed) {
    gemm_body<true>(blockIdx.x % nbx, blockIdx.x / nbx, A, B, C, M, N, K,
                    bs, bq, gamma, beta, asrc, adst, es, ed);
}

// ---------------- fused GAT: single-pass softmax, predicated x4 unroll ----------------
// Lanes >= n carry w0=w1=0 and sreg=0, so GBODY for j >= n contributes exactly 0
// (gathers row 0 with zero weight). Rounding the trip count to a multiple of 4
// gives MLP=4 for EVERY node (avg degree ~11 => the old remainder path dominated).
#define GBODY(jj)                                                        \
    {                                                                    \
        int s_ = __shfl_sync(0xffffffffu, sreg, (jj));                   \
        float ww0_ = __shfl_sync(0xffffffffu, w0, (jj));                 \
        float ww1_ = __shfl_sync(0xffffffffu, w1, (jj));                 \
        const float* hp_ = h + (long)s_ * C;                             \
        if (C == 128) {                                                  \
            float4 hv = *(const float4*)(hp_ + lane * 4);                \
            float w_ = (lane < 16) ? ww0_ : ww1_;                        \
            acc0.x = fmaf(hv.x, w_, acc0.x);                             \
            acc0.y = fmaf(hv.y, w_, acc0.y);                             \
            acc0.z = fmaf(hv.z, w_, acc0.z);                             \
            acc0.w = fmaf(hv.w, w_, acc0.w);                             \
        } else {                                                         \
            float4 hv0 = *(const float4*)(hp_ + lane * 4);               \
            float4 hv1 = *(const float4*)(hp_ + 128 + lane * 4);         \
            acc0.x = fmaf(hv0.x, ww0_, acc0.x);                          \
            acc0.y = fmaf(hv0.y, ww0_, acc0.y);                          \
            acc0.z = fmaf(hv0.z, ww0_, acc0.z);                          \
            acc0.w = fmaf(hv0.w, ww0_, acc0.w);                          \
            acc1.x = fmaf(hv1.x, ww1_, acc1.x);                          \
            acc1.y = fmaf(hv1.y, ww1_, acc1.y);                          \
            acc1.z = fmaf(hv1.z, ww1_, acc1.z);                          \
            acc1.w = fmaf(hv1.w, ww1_, acc1.w);                          \
        }                                                                \
    }

template <int C>
__global__ __launch_bounds__(512, 3)
void fused_gat(const int* __restrict__ off, const int* __restrict__ csrc,
               const float* __restrict__ es, const float* __restrict__ ed,
               const float* __restrict__ h, const float* __restrict__ bias,
               float* __restrict__ y,
               float* __restrict__ bnsum, float* __restrict__ bnsq) {
    __shared__ float ssum[C];
    __shared__ float ssq[C];
    const int tid = threadIdx.x;
    for (int i = tid; i < C; i += 512) { ssum[i] = 0.f; ssq[i] = 0.f; }
    __syncthreads();

    int t = blockIdx.x * 16 + (tid >> 5);
    int lane = tid & 31;
    bool valid = t < NN;
    int b = 0, e = 0;
    float ed0 = 0.f, ed1 = 0.f;
    if (valid) {
        b = off[t];
        e = off[t + 1];
        ed0 = ed[t * 2];
        ed1 = ed[t * 2 + 1];
    }

    float den0 = 0.f, den1 = 0.f;
    float4 acc0 = make_float4(0.f, 0.f, 0.f, 0.f);
    float4 acc1 = make_float4(0.f, 0.f, 0.f, 0.f);
    for (int base = b; base < e; base += 32) {
        int n = min(32, e - base);
        float w0 = 0.f, w1 = 0.f;
        int sreg = 0;
        if (lane < n) {
            sreg = csrc[base + lane];
            float2 esv = *(const float2*)(es + sreg * 2);
            float v0 = esv.x + ed0; v0 = v0 > 0.f ? v0 : 0.2f * v0;
            float v1 = esv.y + ed1; v1 = v1 > 0.f ? v1 : 0.2f * v1;
            w0 = __expf(v0);
            w1 = __expf(v1);
            den0 += w0;
            den1 += w1;
        }
        int pad = (n + 3) & ~3;   // round up: extra iterations contribute exact zeros
        #pragma unroll 1
        for (int j = 0; j < pad; j += 4) {
            GBODY(j)
            GBODY(j + 1)
            GBODY(j + 2)
            GBODY(j + 3)
        }
    }
    #pragma unroll
    for (int o = 16; o; o >>= 1) {
        den0 += __shfl_xor_sync(0xffffffffu, den0, o);
        den1 += __shfl_xor_sync(0xffffffffu, den1, o);
    }

    if (valid) {
        float r0 = 1.f / (den0 + 1e-16f);
        float r1 = 1.f / (den1 + 1e-16f);
        if (C == 128) {
            float r = (lane < 16) ? r0 : r1;
            int c = lane * 4;
            const float4 bb = *(const float4*)(bias + c);
            float4 o = make_float4(acc0.x * r + bb.x, acc0.y * r + bb.y,
                                   acc0.z * r + bb.z, acc0.w * r + bb.w);
            *(float4*)(y + (long)t * C + c) = o;
            atomicAdd(&ssum[c + 0], o.x); atomicAdd(&ssq[c + 0], o.x * o.x);
            atomicAdd(&ssum[c + 1], o.y); atomicAdd(&ssq[c + 1], o.y * o.y);
            atomicAdd(&ssum[c + 2], o.z); atomicAdd(&ssq[c + 2], o.z * o.z);
            atomicAdd(&ssum[c + 3], o.w); atomicAdd(&ssq[c + 3], o.w * o.w);
        } else {
            int c0 = lane * 4, c1 = 128 + lane * 4;
            const float4 b0 = *(const float4*)(bias + c0);
            const float4 b1 = *(const float4*)(bias + c1);
            float4 o0 = make_float4(acc0.x * r0 + b0.x, acc0.y * r0 + b0.y,
                                    acc0.z * r0 + b0.z, acc0.w * r0 + b0.w);
            float4 o1 = make_float4(acc1.x * r1 + b1.x, acc1.y * r1 + b1.y,
                                    acc1.z * r1 + b1.z, acc1.w * r1 + b1.w);
            *(float4*)(y + (long)t * C + c0) = o0;
            *(float4*)(y + (long)t * C + c1) = o1;
            atomicAdd(&ssum[c0 + 0], o0.x); atomicAdd(&ssq[c0 + 0], o0.x * o0.x);
            atomicAdd(&ssum[c0 + 1], o0.y); atomicAdd(&ssq[c0 + 1], o0.y * o0.y);
            atomicAdd(&ssum[c0 + 2], o0.z); atomicAdd(&ssq[c0 + 2], o0.z * o0.z);
            atomicAdd(&ssum[c0 + 3], o0.w); atomicAdd(&ssq[c0 + 3], o0.w * o0.w);
            atomicAdd(&ssum[c1 + 0], o1.x); atomicAdd(&ssq[c1 + 0], o1.x * o1.x);
            atomicAdd(&ssum[c1 + 1], o1.y); atomicAdd(&ssq[c1 + 1], o1.y * o1.y);
            atomicAdd(&ssum[c1 + 2], o1.z); atomicAdd(&ssq[c1 + 2], o1.z * o1.z);
            atomicAdd(&ssum[c1 + 3], o1.w); atomicAdd(&ssq[c1 + 3], o1.w * o1.w);
        }
    }
    __syncthreads();
    for (int i = tid; i < C; i += 512) {
        atomicAdd(&bnsum[i], ssum[i]);
        atomicAdd(&bnsq[i], ssq[i]);
    }
}

// ---------------- pooling: one block per graph; fused BN2-finalize + relu ----------------
__global__ void pool_bn(const float* __restrict__ y2, const int* __restrict__ gstart,
                        const float* __restrict__ bs, const float* __restrict__ bq,
                        const float* __restrict__ gamma, const float* __restrict__ beta,
                        float* __restrict__ pooled) {
    int c = threadIdx.x;  // 256
    float m = bs[c] / (float)NN;
    float var = bq[c] / (float)NN - m * m;
    float sc = rsqrtf(var + 1e-5f) * gamma[c];
    float sh = beta[c] - m * sc;
    int g = blockIdx.x;
    int b = gstart[g], e = gstart[g + 1];
    float s = 0.f;
    for (int r = b; r < e; r++) s += fmaxf(fmaf(y2[(long)r * 256 + c], sc, sh), 0.f);
    pooled[g * 256 + c] = s / fmaxf((float)(e - b), 1.f);
}

// ---------------- FC head ----------------
__global__ void fc_kernel(const float* __restrict__ in, const float* __restrict__ W,
                          const float* __restrict__ b, float* __restrict__ out,
                          int M, int N, int K) {
    int idx = blockIdx.x * blockDim.x + threadIdx.x;
    if (idx >= M * N) return;
    int r = idx / N, c = idx % N;
    float s = b[c];
    for (int k = 0; k < K; k++) s += in[r * K + k] * W[k * N + c];
    out[idx] = s;
}

__global__ void bn_small_relu(const float* __restrict__ in, const float* __restrict__ g,
                              const float* __restrict__ b, float* __restrict__ out, int C) {
    int c = blockIdx.x * blockDim.x + threadIdx.x;
    if (c >= C) return;
    float s = 0.f, sq = 0.f;
    for (int r = 0; r < GG; r++) {
        float v = in[r * C + c];
        s += v;
        sq += v * v;
    }
    float mu = s / (float)GG;
    float rstd = rsqrtf(sq / (float)GG - mu * mu + 1e-5f);
    for (int r = 0; r < GG; r++) {
        float v = (in[r * C + c] - mu) * rstd * g[c] + b[c];
        out[r * C + c] = fmaxf(v, 0.f);
    }
}

// BN over z2 + final linear, single block
__global__ void bn2_final(const float* __restrict__ z2, const float* __restrict__ g2,
                          const float* __restrict__ b2, const float* __restrict__ Wout,
                          const float* __restrict__ bout, float* __restrict__ z2n,
                          float* __restrict__ out) {
    int c = threadIdx.x;  // 256
    float s = 0.f, sq = 0.f;
    for (int r = 0; r < GG; r++) {
        float v = z2[r * 256 + c];
        s += v;
        sq += v * v;
    }
    float mu = s / (float)GG;
    float rstd = rsqrtf(sq / (float)GG - mu * mu + 1e-5f);
    for (int r = 0; r < GG; r++) {
        float v = (z2[r * 256 + c] - mu) * rstd * g2[c] + b2[c];
        z2n[r * 256 + c] = fmaxf(v, 0.f);
    }
    __syncthreads();
    if (c < GG) {
        float acc = bout[0];
        for (int k = 0; k < 256; k++) acc += z2n[c * 256 + k] * Wout[k];
        out[c] = acc;
    }
}

// ---------------- tail cleanup ----------------
__global__ void cleanup(int* __restrict__ deg, float* __restrict__ es1, float* __restrict__ ed1,
                        float* __restrict__ es2, float* __restrict__ ed2,
                        float* __restrict__ bs1, float* __restrict__ bq1,
                        float* __restrict__ bs2, float* __restrict__ bq2) {
    int i = blockIdx.x * blockDim.x + threadIdx.x;
    if (i < NN) deg[i] = 0;
    if (i < NN * 2) { es1[i] = 0.f; ed1[i] = 0.f; es2[i] = 0.f; ed2[i] = 0.f; }
    if (i < 128) { bs1[i] = 0.f; bq1[i] = 0.f; }
    if (i < 256) { bs2[i] = 0.f; bq2[i] = 0.f; }
}

// ---------------- host driver ----------------
static inline int cdiv(long a, int b) { return (int)((a + b - 1) / b); }

extern "C" void kernel_launch(void* const* d_in, const int* in_sizes, int n_in,
                              void* d_out, int out_size) {
    const float* x    = (const float*)d_in[0];
    const int*   esrc = (const int*)d_in[1];
    const int*   edst = (const int*)d_in[2];
    const int*   batch= (const int*)d_in[3];
    const float* W1   = (const float*)d_in[4];
    const float* a_s1 = (const float*)d_in[5];
    const float* a_d1 = (const float*)d_in[6];
    const float* b1   = (const float*)d_in[7];
    const float* g1   = (const float*)d_in[8];
    const float* be1  = (const float*)d_in[9];
    const float* W2   = (const float*)d_in[10];
    const float* a_s2 = (const float*)d_in[11];
    const float* a_d2 = (const float*)d_in[12];
    const float* b2   = (const float*)d_in[13];
    const float* g2   = (const float*)d_in[14];
    const float* be2  = (const float*)d_in[15];
    const float* Wf1  = (const float*)d_in[16];
    const float* bf1  = (const float*)d_in[17];
    const float* gf1  = (const float*)d_in[18];
    const float* bef1 = (const float*)d_in[19];
    const float* Wf2  = (const float*)d_in[20];
    const float* bf2  = (const float*)d_in[21];
    const float* gf2  = (const float*)d_in[22];
    const float* bef2 = (const float*)d_in[23];
    const float* Wout = (const float*)d_in[24];
    const float* bout = (const float*)d_in[25];
    float* out = (float*)d_out;

    float *h1, *y1, *h2, *y2, *es1, *ed1, *es2, *ed2;
    int *deg, *off, *cursor, *csrc, *gstart;
    float *bs1, *bq1, *bs2, *bq2, *pooled, *z1, *z1n, *z2, *z2n;
    cudaGetSymbolAddress((void**)&h1, d_h1);
    cudaGetSymbolAddress((void**)&y1, d_y1);
    cudaGetSymbolAddress((void**)&h2, d_h2);
    cudaGetSymbolAddress((void**)&y2, d_y2);
    cudaGetSymbolAddress((void**)&es1, d_es1);
    cudaGetSymbolAddress((void**)&ed1, d_ed1);
    cudaGetSymbolAddress((void**)&es2, d_es2);
    cudaGetSymbolAddress((void**)&ed2, d_ed2);
    cudaGetSymbolAddress((void**)&deg, d_deg);
    cudaGetSymbolAddress((void**)&off, d_off);
    cudaGetSymbolAddress((void**)&cursor, d_cursor);
    cudaGetSymbolAddress((void**)&csrc, d_csrc);
    cudaGetSymbolAddress((void**)&gstart, d_gstart);
    cudaGetSymbolAddress((void**)&bs1, d_bs1);
    cudaGetSymbolAddress((void**)&bq1, d_bq1);
    cudaGetSymbolAddress((void**)&bs2, d_bs2);
    cudaGetSymbolAddress((void**)&bq2, d_bq2);
    cudaGetSymbolAddress((void**)&pooled, d_pooled);
    cudaGetSymbolAddress((void**)&z1, d_z1);
    cudaGetSymbolAddress((void**)&z1n, d_z1n);
    cudaGetSymbolAddress((void**)&z2, d_z2);
    cudaGetSymbolAddress((void**)&z2n, d_z2n);

    const int TB = 256;

    // 1: degree count
    count_deg<<<cdiv(EE, TB), TB>>>(edst, deg);
    // 2: offsets scan (+1 self-loop folded in)
    scan_offsets<<<1, 1024>>>(deg, off, cursor);
    // 3: gemm1 + CSR fill + graph bounds
    combo1<<<GEMM1_BLOCKS + CSR_BLOCKS + 1, 256>>>(x, W1, h1, a_s1, a_d1, es1, ed1,
                                                   esrc, edst, cursor, csrc, batch, gstart);
    // 4: fused GAT layer 1  (ncu window)
    fused_gat<128><<<cdiv(NN, 16), 512>>>(off, csrc, es1, ed1, h1, b1, y1, bs1, bq1);
    // 5: gemm2 (BN1 finalize+apply fused)
    gemm_k<<<4 * cdiv(NN, 128), 256>>>(4, y1, W2, h2, NN, 256, 128,
                                       bs1, bq1, g1, be1, a_s2, a_d2, es2, ed2);
    // 6: fused GAT layer 2
    fused_gat<256><<<cdiv(NN, 16), 512>>>(off, csrc, es2, ed2, h2, b2, y2, bs2, bq2);
    // 7: pool (BN2 finalize+relu fused)
    pool_bn<<<GG, 256>>>(y2, gstart, bs2, bq2, g2, be2, pooled);
    // 8-11: FC head
    fc_kernel<<<cdiv(GG * 512, TB), TB>>>(pooled, Wf1, bf1, z1, GG, 512, 256);
    bn_small_relu<<<2, 256>>>(z1, gf1, bef1, z1n, 512);
    fc_kernel<<<cdiv(GG * 256, TB), TB>>>(z1n, Wf2, bf2, z2, GG, 256, 512);
    bn2_final<<<1, 256>>>(z2, gf2, bef2, Wout, bout, z2n, out);
    // 12: tail cleanup for next replay
    cleanup<<<cdiv(NN * 2, TB), TB>>>(deg, es1, ed1, es2, ed2, bs1, bq1, bs2, bq2);
}

// round 15
// speedup vs baseline: 1.0061x; 1.0061x over previous
#include <cuda_runtime.h>
#include <cuda_bf16.h>

#define NN 50000
#define EE 500000
#define HH 2
#define GG 128

// ---------------- scratch ----------------
__device__ float d_h1[NN * 128];
__device__ float d_y1[NN * 128];
__device__ float d_h2[NN * 256];
__device__ float d_y2[NN * 256];
__device__ float d_es1[NN * 2], d_ed1[NN * 2];
__device__ float d_es2[NN * 2], d_ed2[NN * 2];
__device__ int   d_deg[NN], d_off[NN + 1], d_cursor[NN];
__device__ int   d_csrc[EE + NN];
__device__ int   d_gstart[GG + 1];
__device__ float d_bs1[128], d_bq1[128];
__device__ float d_bs2[256], d_bq2[256];
__device__ float d_pooled[GG * 256];
__device__ float d_z1[GG * 512], d_z1n[GG * 512];
__device__ float d_z2[GG * 256], d_z2n[GG * 256];

static const int GEMM1_BLOCKS = 2 * ((NN + 127) / 128);            // 782
static const int CSR_BLOCKS = (EE + NN + 255) / 256;               // 2149

// ---------------- CSR: degree count ----------------
__global__ void count_deg(const int* __restrict__ dst, int* __restrict__ deg) {
    int e = blockIdx.x * blockDim.x + threadIdx.x;
    if (e < EE) atomicAdd(&deg[dst[e]], 1);
}

// single-block scan; degree = deg[i] + 1 (implicit self-loop)
__global__ void scan_offsets(const int* __restrict__ deg, int* __restrict__ off,
                             int* __restrict__ cursor) {
    __shared__ int part[1024];
    const int CH = (NN + 1023) / 1024;
    int t = threadIdx.x;
    int base = t * CH;
    int s = 0;
    for (int i = 0; i < CH; i++) {
        int idx = base + i;
        if (idx < NN) s += deg[idx] + 1;
    }
    part[t] = s;
    __syncthreads();
    for (int d = 1; d < 1024; d <<= 1) {
        int v = (t >= d) ? part[t - d] : 0;
        __syncthreads();
        part[t] += v;
        __syncthreads();
    }
    int run = (t == 0) ? 0 : part[t - 1];
    for (int i = 0; i < CH; i++) {
        int idx = base + i;
        if (idx < NN) {
            off[idx] = run;
            cursor[idx] = run;
            run += deg[idx] + 1;
        }
    }
    if (t == 1023) off[NN] = part[1023];
}

// ---------------- tf32 GEMM body ----------------
__device__ __forceinline__ unsigned f2tf(float f) {
    unsigned r;
    asm("cvt.rna.tf32.f32 %0, %1;" : "=r"(r) : "f"(f));
    return r;
}
__device__ __forceinline__ void mma_tf32(float4& c, const unsigned* a, const unsigned* b) {
    asm volatile(
        "mma.sync.aligned.m16n8k8.row.col.f32.tf32.tf32.f32 "
        "{%0,%1,%2,%3}, {%4,%5,%6,%7}, {%8,%9}, {%0,%1,%2,%3};"
        : "+f"(c.x), "+f"(c.y), "+f"(c.z), "+f"(c.w)
        : "r"(a[0]), "r"(a[1]), "r"(a[2]), "r"(a[3]), "r"(b[0]), "r"(b[1]));
}

template <bool APPLY_BN>
__device__ void gemm_body(int bx, int by,
                          const float* __restrict__ A, const float* __restrict__ B,
                          float* __restrict__ C, int M, int N, int K,
                          const float* __restrict__ bs, const float* __restrict__ bq,
                          const float* __restrict__ gamma, const float* __restrict__ beta,
                          const float* __restrict__ asrc, const float* __restrict__ adst,
                          float* __restrict__ es, float* __restrict__ ed) {
    __shared__ unsigned As[128][17];
    __shared__ unsigned Bs[16][72];
    __shared__ float sscale[128], sshift[128];
    const int brow = by * 128;
    const int bcol = bx * 64;
    const int tid = threadIdx.x;
    const int w = tid >> 5, l = tid & 31;
    const int wm = w & 3, wn = w >> 2;
    const int mbase = wm * 32, nbase = wn * 32;
    const int g = l >> 2, tg = l & 3;

    if (APPLY_BN) {
        if (tid < K) {
            float m = bs[tid] / (float)NN;
            float var = bq[tid] / (float)NN - m * m;
            float sc = rsqrtf(var + 1e-5f) * gamma[tid];
            sscale[tid] = sc;
            sshift[tid] = beta[tid] - m * sc;
        }
        __syncthreads();
    }

    float4 acc[2][4];
    #pragma unroll
    for (int i = 0; i < 2; i++)
        #pragma unroll
        for (int j = 0; j < 4; j++) acc[i][j] = make_float4(0.f, 0.f, 0.f, 0.f);

    for (int k0 = 0; k0 < K; k0 += 16) {
        #pragma unroll
        for (int i = tid; i < 512; i += 256) {
            int r = i >> 2, c4 = (i & 3) * 4;
            int gr = brow + r;
            float4 v = make_float4(0.f, 0.f, 0.f, 0.f);
            if (gr < M) {
                v = *(const float4*)(A + (long)gr * K + k0 + c4);
                if (APPLY_BN) {
                    int c = k0 + c4;
                    v.x = fmaxf(fmaf(v.x, sscale[c + 0], sshift[c + 0]), 0.f);
                    v.y = fmaxf(fmaf(v.y, sscale[c + 1], sshift[c + 1]), 0.f);
                    v.z = fmaxf(fmaf(v.z, sscale[c + 2], sshift[c + 2]), 0.f);
                    v.w = fmaxf(fmaf(v.w, sscale[c + 3], sshift[c + 3]), 0.f);
                }
            }
            As[r][c4 + 0] = f2tf(v.x);
            As[r][c4 + 1] = f2tf(v.y);
            As[r][c4 + 2] = f2tf(v.z);
            As[r][c4 + 3] = f2tf(v.w);
        }
        {
            int r = tid >> 4, c4 = (tid & 15) * 4;
            float4 v = *(const float4*)(B + (long)(k0 + r) * N + bcol + c4);
            Bs[r][c4 + 0] = f2tf(v.x);
            Bs[r][c4 + 1] = f2tf(v.y);
            Bs[r][c4 + 2] = f2tf(v.z);
            Bs[r][c4 + 3] = f2tf(v.w);
        }
        __syncthreads();
        #pragma unroll
        for (int k8 = 0; k8 < 16; k8 += 8) {
            unsigned af[2][4], bf[4][2];
            #pragma unroll
            for (int mt = 0; mt < 2; mt++) {
                int r0 = mbase + mt * 16 + g;
                int c = k8 + tg;
                af[mt][0] = As[r0][c];
                af[mt][1] = As[r0 + 8][c];
                af[mt][2] = As[r0][c + 4];
                af[mt][3] = As[r0 + 8][c + 4];
            }
            #pragma unroll
            for (int nt = 0; nt < 4; nt++) {
                int cb = nbase + nt * 8 + g;
                int rb = k8 + tg;
                bf[nt][0] = Bs[rb][cb];
                bf[nt][1] = Bs[rb + 4][cb];
            }
            #pragma unroll
            for (int mt = 0; mt < 2; mt++)
                #pragma unroll
                for (int nt = 0; nt < 4; nt++) mma_tf32(acc[mt][nt], af[mt], bf[nt]);
        }
        __syncthreads();
    }

    #pragma unroll
    for (int mt = 0; mt < 2; mt++) {
        #pragma unroll
        for (int nt = 0; nt < 4; nt++) {
            int row = brow + mbase + mt * 16 + g;
            int col = bcol + nbase + nt * 8 + 2 * tg;
            if (row < M)
                *(float2*)(C + (long)row * N + col) = make_float2(acc[mt][nt].x, acc[mt][nt].y);
            if (row + 8 < M)
                *(float2*)(C + (long)(row + 8) * N + col) = make_float2(acc[mt][nt].z, acc[mt][nt].w);
        }
    }

    // fused attention-logit epilogue
    {
        int head = (2 * bcol >= N) ? 1 : 0;
        float av_s[8], av_d[8];
        #pragma unroll
        for (int nt = 0; nt < 4; nt++) {
            int col = bcol + nbase + nt * 8 + 2 * tg;
            av_s[nt * 2 + 0] = __ldg(asrc + col);
            av_s[nt * 2 + 1] = __ldg(asrc + col + 1);
            av_d[nt * 2 + 0] = __ldg(adst + col);
            av_d[nt * 2 + 1] = __ldg(adst + col + 1);
        }
        #pragma unroll
        for (int mt = 0; mt < 2; mt++) {
            float pes0 = 0.f, ped0 = 0.f, pes8 = 0.f, ped8 = 0.f;
            #pragma unroll
            for (int nt = 0; nt < 4; nt++) {
                float4 a = acc[mt][nt];
                pes0 += a.x * av_s[nt * 2] + a.y * av_s[nt * 2 + 1];
                ped0 += a.x * av_d[nt * 2] + a.y * av_d[nt * 2 + 1];
                pes8 += a.z * av_s[nt * 2] + a.w * av_s[nt * 2 + 1];
                ped8 += a.z * av_d[nt * 2] + a.w * av_d[nt * 2 + 1];
            }
            #pragma unroll
            for (int o = 1; o <= 2; o <<= 1) {
                pes0 += __shfl_xor_sync(0xffffffffu, pes0, o);
                ped0 += __shfl_xor_sync(0xffffffffu, ped0, o);
                pes8 += __shfl_xor_sync(0xffffffffu, pes8, o);
                ped8 += __shfl_xor_sync(0xffffffffu, ped8, o);
            }
            if (tg == 0) {
                int row = brow + mbase + mt * 16 + g;
                if (row < M) {
                    atomicAdd(&es[row * 2 + head], pes0);
                    atomicAdd(&ed[row * 2 + head], ped0);
                }
                if (row + 8 < M) {
                    atomicAdd(&es[(row + 8) * 2 + head], pes8);
                    atomicAdd(&ed[(row + 8) * 2 + head], ped8);
                }
            }
        }
    }
}

// ---------------- combo: gemm1 tiles + CSR fill + graph bounds ----------------
__global__ void combo1(const float* __restrict__ x, const float* __restrict__ W1,
                       float* __restrict__ h1,
                       const float* __restrict__ a_s1, const float* __restrict__ a_d1,
                       float* __restrict__ es1, float* __restrict__ ed1,
                       const int* __restrict__ esrc, const int* __restrict__ edst,
                       int* __restrict__ cursor, int* __restrict__ csrc,
                       const int* __restrict__ batch, int* __restrict__ gstart) {
    int bid = blockIdx.x;
    if (bid < GEMM1_BLOCKS) {
        gemm_body<false>(bid & 1, bid >> 1, x, W1, h1, NN, 128, 64,
                         nullptr, nullptr, nullptr, nullptr, a_s1, a_d1, es1, ed1);
    } else if (bid < GEMM1_BLOCKS + CSR_BLOCKS) {
        int idx = (bid - GEMM1_BLOCKS) * 256 + threadIdx.x;
        if (idx < EE) {
            int t = edst[idx];
            int p = atomicAdd(&cursor[t], 1);
            csrc[p] = esrc[idx];
        } else if (idx < EE + NN) {
            int n = idx - EE;
            int p = atomicAdd(&cursor[n], 1);
            csrc[p] = n;
        }
    } else {
        int g = threadIdx.x;
        if (g <= GG) {
            int lo = 0, hi = NN;
            while (lo < hi) {
                int mid = (lo + hi) >> 1;
                if (batch[mid] < g) lo = mid + 1; else hi = mid;
            }
            gstart[g] = lo;
        }
    }
}

__global__ void gemm_k(int nbx, const float* A, const float* B, float* C, int M, int N, int K,
                       const float* bs, const float* bq, const float* gamma, const float* beta,
                       const float* asrc, const float* adst, float* es, float* ed) {
    gemm_body<true>(blockIdx.x % nbx, blockIdx.x / nbx, A, B, C, M, N, K,
                    bs, bq, gamma, beta, asrc, adst, es, ed);
}

// ---------------- fused GAT: single-pass softmax (R13 form), occupancy 4 blocks/SM ----------------
#define GBODY(jj)                                                        \
    {                                                                    \
        int s_ = __shfl_sync(0xffffffffu, sreg, (jj));                   \
        float ww0_ = __shfl_sync(0xffffffffu, w0, (jj));                 \
        float ww1_ = __shfl_sync(0xffffffffu, w1, (jj));                 \
        const float* hp_ = h + (long)s_ * C;                             \
        if (C == 128) {                                                  \
            float4 hv = *(const float4*)(hp_ + lane * 4);                \
            float w_ = (lane < 16) ? ww0_ : ww1_;                        \
            acc0.x = fmaf(hv.x, w_, acc0.x);                             \
            acc0.y = fmaf(hv.y, w_, acc0.y);                             \
            acc0.z = fmaf(hv.z, w_, acc0.z);                             \
            acc0.w = fmaf(hv.w, w_, acc0.w);                             \
        } else {                                                         \
            float4 hv0 = *(const float4*)(hp_ + lane * 4);               \
            float4 hv1 = *(const float4*)(hp_ + 128 + lane * 4);         \
            acc0.x = fmaf(hv0.x, ww0_, acc0.x);                          \
            acc0.y = fmaf(hv0.y, ww0_, acc0.y);                          \
            acc0.z = fmaf(hv0.z, ww0_, acc0.z);                          \
            acc0.w = fmaf(hv0.w, ww0_, acc0.w);                          \
            acc1.x = fmaf(hv1.x, ww1_, acc1.x);                          \
            acc1.y = fmaf(hv1.y, ww1_, acc1.y);                          \
            acc1.z = fmaf(hv1.z, ww1_, acc1.z);                          \
            acc1.w = fmaf(hv1.w, ww1_, acc1.w);                          \
        }                                                                \
    }

template <int C>
__global__ __launch_bounds__(512, 4)
void fused_gat(const int* __restrict__ off, const int* __restrict__ csrc,
               const float* __restrict__ es, const float* __restrict__ ed,
               const float* __restrict__ h, const float* __restrict__ bias,
               float* __restrict__ y,
               float* __restrict__ bnsum, float* __restrict__ bnsq) {
    __shared__ float ssum[C];
    __shared__ float ssq[C];
    const int tid = threadIdx.x;
    for (int i = tid; i < C; i += 512) { ssum[i] = 0.f; ssq[i] = 0.f; }
    __syncthreads();

    int t = blockIdx.x * 16 + (tid >> 5);
    int lane = tid & 31;
    bool valid = t < NN;
    int b = 0, e = 0;
    float ed0 = 0.f, ed1 = 0.f;
    if (valid) {
        b = off[t];
        e = off[t + 1];
        ed0 = ed[t * 2];
        ed1 = ed[t * 2 + 1];
    }

    // single pass: exp weights + denom + gather (no max shift; logits O(1))
    float den0 = 0.f, den1 = 0.f;
    float4 acc0 = make_float4(0.f, 0.f, 0.f, 0.f);
    float4 acc1 = make_float4(0.f, 0.f, 0.f, 0.f);
    for (int base = b; base < e; base += 32) {
        int n = min(32, e - base);
        float w0 = 0.f, w1 = 0.f;
        int sreg = 0;
        if (lane < n) {
            sreg = csrc[base + lane];
            float2 esv = *(const float2*)(es + sreg * 2);
            float v0 = esv.x + ed0; v0 = v0 > 0.f ? v0 : 0.2f * v0;
            float v1 = esv.y + ed1; v1 = v1 > 0.f ? v1 : 0.2f * v1;
            w0 = __expf(v0);
            w1 = __expf(v1);
            den0 += w0;
            den1 += w1;
        }
        if (n == 32) {
            #pragma unroll 1
            for (int j = 0; j < 32; j += 4) {
                GBODY(j)
                GBODY(j + 1)
                GBODY(j + 2)
                GBODY(j + 3)
            }
        } else {
            for (int j = 0; j < n; j++) GBODY(j)
        }
    }
    #pragma unroll
    for (int o = 16; o; o >>= 1) {
        den0 += __shfl_xor_sync(0xffffffffu, den0, o);
        den1 += __shfl_xor_sync(0xffffffffu, den1, o);
    }

    if (valid) {
        float r0 = 1.f / (den0 + 1e-16f);
        float r1 = 1.f / (den1 + 1e-16f);
        if (C == 128) {
            float r = (lane < 16) ? r0 : r1;
            int c = lane * 4;
            const float4 bb = *(const float4*)(bias + c);
            float4 o = make_float4(acc0.x * r + bb.x, acc0.y * r + bb.y,
                                   acc0.z * r + bb.z, acc0.w * r + bb.w);
            *(float4*)(y + (long)t * C + c) = o;
            atomicAdd(&ssum[c + 0], o.x); atomicAdd(&ssq[c + 0], o.x * o.x);
            atomicAdd(&ssum[c + 1], o.y); atomicAdd(&ssq[c + 1], o.y * o.y);
            atomicAdd(&ssum[c + 2], o.z); atomicAdd(&ssq[c + 2], o.z * o.z);
            atomicAdd(&ssum[c + 3], o.w); atomicAdd(&ssq[c + 3], o.w * o.w);
        } else {
            int c0 = lane * 4, c1 = 128 + lane * 4;
            const float4 b0 = *(const float4*)(bias + c0);
            const float4 b1 = *(const float4*)(bias + c1);
            float4 o0 = make_float4(acc0.x * r0 + b0.x, acc0.y * r0 + b0.y,
                                    acc0.z * r0 + b0.z, acc0.w * r0 + b0.w);
            float4 o1 = make_float4(acc1.x * r1 + b1.x, acc1.y * r1 + b1.y,
                                    acc1.z * r1 + b1.z, acc1.w * r1 + b1.w);
            *(float4*)(y + (long)t * C + c0) = o0;
            *(float4*)(y + (long)t * C + c1) = o1;
            atomicAdd(&ssum[c0 + 0], o0.x); atomicAdd(&ssq[c0 + 0], o0.x * o0.x);
            atomicAdd(&ssum[c0 + 1], o0.y); atomicAdd(&ssq[c0 + 1], o0.y * o0.y);
            atomicAdd(&ssum[c0 + 2], o0.z); atomicAdd(&ssq[c0 + 2], o0.z * o0.z);
            atomicAdd(&ssum[c0 + 3], o0.w); atomicAdd(&ssq[c0 + 3], o0.w * o0.w);
            atomicAdd(&ssum[c1 + 0], o1.x); atomicAdd(&ssq[c1 + 0], o1.x * o1.x);
            atomicAdd(&ssum[c1 + 1], o1.y); atomicAdd(&ssq[c1 + 1], o1.y * o1.y);
            atomicAdd(&ssum[c1 + 2], o1.z); atomicAdd(&ssq[c1 + 2], o1.z * o1.z);
            atomicAdd(&ssum[c1 + 3], o1.w); atomicAdd(&ssq[c1 + 3], o1.w * o1.w);
        }
    }
    __syncthreads();
    for (int i = tid; i < C; i += 512) {
        atomicAdd(&bnsum[i], ssum[i]);
        atomicAdd(&bnsq[i], ssq[i]);
    }
}

// ---------------- pooling: one block per graph; fused BN2-finalize + relu ----------------
__global__ void pool_bn(const float* __restrict__ y2, const int* __restrict__ gstart,
                        const float* __restrict__ bs, const float* __restrict__ bq,
                        const float* __restrict__ gamma, const float* __restrict__ beta,
                        float* __restrict__ pooled) {
    int c = threadIdx.x;  // 256
    float m = bs[c] / (float)NN;
    float var = bq[c] / (float)NN - m * m;
    float sc = rsqrtf(var + 1e-5f) * gamma[c];
    float sh = beta[c] - m * sc;
    int g = blockIdx.x;
    int b = gstart[g], e = gstart[g + 1];
    float s = 0.f;
    for (int r = b; r < e; r++) s += fmaxf(fmaf(y2[(long)r * 256 + c], sc, sh), 0.f);
    pooled[g * 256 + c] = s / fmaxf((float)(e - b), 1.f);
}

// ---------------- FC head ----------------
__global__ void fc_kernel(const float* __restrict__ in, const float* __restrict__ W,
                          const float* __restrict__ b, float* __restrict__ out,
                          int M, int N, int K) {
    int idx = blockIdx.x * blockDim.x + threadIdx.x;
    if (idx >= M * N) return;
    int r = idx / N, c = idx % N;
    float s = b[c];
    for (int k = 0; k < K; k++) s += in[r * K + k] * W[k * N + c];
    out[idx] = s;
}

__global__ void bn_small_relu(const float* __restrict__ in, const float* __restrict__ g,
                              const float* __restrict__ b, float* __restrict__ out, int C) {
    int c = blockIdx.x * blockDim.x + threadIdx.x;
    if (c >= C) return;
    float s = 0.f, sq = 0.f;
    for (int r = 0; r < GG; r++) {
        float v = in[r * C + c];
        s += v;
        sq += v * v;
    }
    float mu = s / (float)GG;
    float rstd = rsqrtf(sq / (float)GG - mu * mu + 1e-5f);
    for (int r = 0; r < GG; r++) {
        float v = (in[r * C + c] - mu) * rstd * g[c] + b[c];
        out[r * C + c] = fmaxf(v, 0.f);
    }
}

// BN over z2 + final linear, single block
__global__ void bn2_final(const float* __restrict__ z2, const float* __restrict__ g2,
                          const float* __restrict__ b2, const float* __restrict__ Wout,
                          const float* __restrict__ bout, float* __restrict__ z2n,
                          float* __restrict__ out) {
    int c = threadIdx.x;  // 256
    float s = 0.f, sq = 0.f;
    for (int r = 0; r < GG; r++) {
        float v = z2[r * 256 + c];
        s += v;
        sq += v * v;
    }
    float mu = s / (float)GG;
    float rstd = rsqrtf(sq / (float)GG - mu * mu + 1e-5f);
    for (int r = 0; r < GG; r++) {
        float v = (z2[r * 256 + c] - mu) * rstd * g2[c] + b2[c];
        z2n[r * 256 + c] = fmaxf(v, 0.f);
    }
    __syncthreads();
    if (c < GG) {
        float acc = bout[0];
        for (int k = 0; k < 256; k++) acc += z2n[c * 256 + k] * Wout[k];
        out[c] = acc;
    }
}

// ---------------- tail cleanup ----------------
__global__ void cleanup(int* __restrict__ deg, float* __restrict__ es1, float* __restrict__ ed1,
                        float* __restrict__ es2, float* __restrict__ ed2,
                        float* __restrict__ bs1, float* __restrict__ bq1,
                        float* __restrict__ bs2, float* __restrict__ bq2) {
    int i = blockIdx.x * blockDim.x + threadIdx.x;
    if (i < NN) deg[i] = 0;
    if (i < NN * 2) { es1[i] = 0.f; ed1[i] = 0.f; es2[i] = 0.f; ed2[i] = 0.f; }
    if (i < 128) { bs1[i] = 0.f; bq1[i] = 0.f; }
    if (i < 256) { bs2[i] = 0.f; bq2[i] = 0.f; }
}

// ---------------- host driver ----------------
static inline int cdiv(long a, int b) { return (int)((a + b - 1) / b); }

extern "C" void kernel_launch(void* const* d_in, const int* in_sizes, int n_in,
                              void* d_out, int out_size) {
    const float* x    = (const float*)d_in[0];
    const int*   esrc = (const int*)d_in[1];
    const int*   edst = (const int*)d_in[2];
    const int*   batch= (const int*)d_in[3];
    const float* W1   = (const float*)d_in[4];
    const float* a_s1 = (const float*)d_in[5];
    const float* a_d1 = (const float*)d_in[6];
    const float* b1   = (const float*)d_in[7];
    const float* g1   = (const float*)d_in[8];
    const float* be1  = (const float*)d_in[9];
    const float* W2   = (const float*)d_in[10];
    const float* a_s2 = (const float*)d_in[11];
    const float* a_d2 = (const float*)d_in[12];
    const float* b2   = (const float*)d_in[13];
    const float* g2   = (const float*)d_in[14];
    const float* be2  = (const float*)d_in[15];
    const float* Wf1  = (const float*)d_in[16];
    const float* bf1  = (const float*)d_in[17];
    const float* gf1  = (const float*)d_in[18];
    const float* bef1 = (const float*)d_in[19];
    const float* Wf2  = (const float*)d_in[20];
    const float* bf2  = (const float*)d_in[21];
    const float* gf2  = (const float*)d_in[22];
    const float* bef2 = (const float*)d_in[23];
    const float* Wout = (const float*)d_in[24];
    const float* bout = (const float*)d_in[25];
    float* out = (float*)d_out;

    float *h1, *y1, *h2, *y2, *es1, *ed1, *es2, *ed2;
    int *deg, *off, *cursor, *csrc, *gstart;
    float *bs1, *bq1, *bs2, *bq2, *pooled, *z1, *z1n, *z2, *z2n;
    cudaGetSymbolAddress((void**)&h1, d_h1);
    cudaGetSymbolAddress((void**)&y1, d_y1);
    cudaGetSymbolAddress((void**)&h2, d_h2);
    cudaGetSymbolAddress((void**)&y2, d_y2);
    cudaGetSymbolAddress((void**)&es1, d_es1);
    cudaGetSymbolAddress((void**)&ed1, d_ed1);
    cudaGetSymbolAddress((void**)&es2, d_es2);
    cudaGetSymbolAddress((void**)&ed2, d_ed2);
    cudaGetSymbolAddress((void**)&deg, d_deg);
    cudaGetSymbolAddress((void**)&off, d_off);
    cudaGetSymbolAddress((void**)&cursor, d_cursor);
    cudaGetSymbolAddress((void**)&csrc, d_csrc);
    cudaGetSymbolAddress((void**)&gstart, d_gstart);
    cudaGetSymbolAddress((void**)&bs1, d_bs1);
    cudaGetSymbolAddress((void**)&bq1, d_bq1);
    cudaGetSymbolAddress((void**)&bs2, d_bs2);
    cudaGetSymbolAddress((void**)&bq2, d_bq2);
    cudaGetSymbolAddress((void**)&pooled, d_pooled);
    cudaGetSymbolAddress((void**)&z1, d_z1);
    cudaGetSymbolAddress((void**)&z1n, d_z1n);
    cudaGetSymbolAddress((void**)&z2, d_z2);
    cudaGetSymbolAddress((void**)&z2n, d_z2n);

    const int TB = 256;

    // 1: degree count
    count_deg<<<cdiv(EE, TB), TB>>>(edst, deg);
    // 2: offsets scan (+1 self-loop folded in)
    scan_offsets<<<1, 1024>>>(deg, off, cursor);
    // 3: gemm1 + CSR fill + graph bounds
    combo1<<<GEMM1_BLOCKS + CSR_BLOCKS + 1, 256>>>(x, W1, h1, a_s1, a_d1, es1, ed1,
                                                   esrc, edst, cursor, csrc, batch, gstart);
    // 4: fused GAT layer 1  (ncu window)
    fused_gat<128><<<cdiv(NN, 16), 512>>>(off, csrc, es1, ed1, h1, b1, y1, bs1, bq1);
    // 5: gemm2 (BN1 finalize+apply fused)
    gemm_k<<<4 * cdiv(NN, 128), 256>>>(4, y1, W2, h2, NN, 256, 128,
                                       bs1, bq1, g1, be1, a_s2, a_d2, es2, ed2);
    // 6: fused GAT layer 2
    fused_gat<256><<<cdiv(NN, 16), 512>>>(off, csrc, es2, ed2, h2, b2, y2, bs2, bq2);
    // 7: pool (BN2 finalize+relu fused)
    pool_bn<<<GG, 256>>>(y2, gstart, bs2, bq2, g2, be2, pooled);
    // 8-11: FC head
    fc_kernel<<<cdiv(GG * 512, TB), TB>>>(pooled, Wf1, bf1, z1, GG, 512, 256);
    bn_small_relu<<<2, 256>>>(z1, gf1, bef1, z1n, 512);
    fc_kernel<<<cdiv(GG * 256, TB), TB>>>(z1n, Wf2, bf2, z2, GG, 256, 512);
    bn2_final<<<1, 256>>>(z2, gf2, bef2, Wout, bout, z2n, out);
    // 12: tail cleanup for next replay
    cleanup<<<cdiv(NN * 2, TB), TB>>>(deg, es1, ed1, es2, ed2, bs1, bq1, bs2, bq2);
}

// round 16
// speedup vs baseline: 1.0147x; 1.0086x over previous
#include <cuda_runtime.h>
#include <cuda_bf16.h>

#define NN 50000
#define EE 500000
#define HH 2
#define GG 128

// ---------------- scratch ----------------
__device__ float d_h1[NN * 128];
__device__ float d_y1[NN * 128];
__device__ float d_h2[NN * 256];
__device__ float d_y2[NN * 256];
__device__ float d_es1[NN * 2], d_ed1[NN * 2];
__device__ float d_es2[NN * 2], d_ed2[NN * 2];
__device__ int   d_deg[NN], d_off[NN + 1], d_cursor[NN];
__device__ int   d_csrc[EE + NN];
__device__ int   d_gstart[GG + 1];
__device__ float d_bs1[128], d_bq1[128];
__device__ float d_bs2[256], d_bq2[256];
__device__ float d_pooled[GG * 256];
__device__ float d_z1[GG * 512], d_z1n[GG * 512];
__device__ float d_z2[GG * 256], d_z2n[GG * 256];

static const int GEMM1_BLOCKS = 2 * ((NN + 127) / 128);            // 782
static const int CSR_BLOCKS = (EE + NN + 255) / 256;               // 2149

// ---------------- CSR: degree count ----------------
__global__ void count_deg(const int* __restrict__ dst, int* __restrict__ deg) {
    int e = blockIdx.x * blockDim.x + threadIdx.x;
    if (e < EE) atomicAdd(&deg[dst[e]], 1);
}

// single-block scan; degree = deg[i] + 1 (implicit self-loop)
__global__ void scan_offsets(const int* __restrict__ deg, int* __restrict__ off,
                             int* __restrict__ cursor) {
    __shared__ int part[1024];
    const int CH = (NN + 1023) / 1024;
    int t = threadIdx.x;
    int base = t * CH;
    int s = 0;
    for (int i = 0; i < CH; i++) {
        int idx = base + i;
        if (idx < NN) s += deg[idx] + 1;
    }
    part[t] = s;
    __syncthreads();
    for (int d = 1; d < 1024; d <<= 1) {
        int v = (t >= d) ? part[t - d] : 0;
        __syncthreads();
        part[t] += v;
        __syncthreads();
    }
    int run = (t == 0) ? 0 : part[t - 1];
    for (int i = 0; i < CH; i++) {
        int idx = base + i;
        if (idx < NN) {
            off[idx] = run;
            cursor[idx] = run;
            run += deg[idx] + 1;
        }
    }
    if (t == 1023) off[NN] = part[1023];
}

// ---------------- tf32 GEMM body: double-buffered smem, 1 sync per K-slab ----------------
__device__ __forceinline__ unsigned f2tf(float f) {
    unsigned r;
    asm("cvt.rna.tf32.f32 %0, %1;" : "=r"(r) : "f"(f));
    return r;
}
__device__ __forceinline__ void mma_tf32(float4& c, const unsigned* a, const unsigned* b) {
    asm volatile(
        "mma.sync.aligned.m16n8k8.row.col.f32.tf32.tf32.f32 "
        "{%0,%1,%2,%3}, {%4,%5,%6,%7}, {%8,%9}, {%0,%1,%2,%3};"
        : "+f"(c.x), "+f"(c.y), "+f"(c.z), "+f"(c.w)
        : "r"(a[0]), "r"(a[1]), "r"(a[2]), "r"(a[3]), "r"(b[0]), "r"(b[1]));
}

template <bool APPLY_BN>
__device__ void gemm_body(int bx, int by,
                          const float* __restrict__ A, const float* __restrict__ B,
                          float* __restrict__ C, int M, int N, int K,
                          const float* __restrict__ bs, const float* __restrict__ bq,
                          const float* __restrict__ gamma, const float* __restrict__ beta,
                          const float* __restrict__ asrc, const float* __restrict__ adst,
                          float* __restrict__ es, float* __restrict__ ed) {
    __shared__ unsigned As[2][128][17];
    __shared__ unsigned Bs[2][16][72];
    __shared__ float sscale[128], sshift[128];
    const int brow = by * 128;
    const int bcol = bx * 64;
    const int tid = threadIdx.x;
    const int w = tid >> 5, l = tid & 31;
    const int wm = w & 3, wn = w >> 2;
    const int mbase = wm * 32, nbase = wn * 32;
    const int g = l >> 2, tg = l & 3;

    // per-thread staging coordinates
    const int ar0 = tid >> 2;            // A row 0 (0..63)
    const int ar1 = ar0 + 64;            // A row 1 (64..127)
    const int ac = (tid & 3) * 4;        // A k-col base
    const int brr = tid >> 4;            // B row (0..15)
    const int bcc = (tid & 15) * 4;      // B col base

    if (APPLY_BN) {
        if (tid < K) {
            float m = bs[tid] / (float)NN;
            float var = bq[tid] / (float)NN - m * m;
            float sc = rsqrtf(var + 1e-5f) * gamma[tid];
            sscale[tid] = sc;
            sshift[tid] = beta[tid] - m * sc;
        }
        __syncthreads();
    }

    float4 acc[2][4];
    #pragma unroll
    for (int i = 0; i < 2; i++)
        #pragma unroll
        for (int j = 0; j < 4; j++) acc[i][j] = make_float4(0.f, 0.f, 0.f, 0.f);

    const int NT = K / 16;

    // ---- load slab 0 into buffer 0 ----
    {
        float4 v0 = make_float4(0.f, 0.f, 0.f, 0.f);
        float4 v1 = make_float4(0.f, 0.f, 0.f, 0.f);
        int gr0 = brow + ar0, gr1 = brow + ar1;
        if (gr0 < M) {
            v0 = *(const float4*)(A + (long)gr0 * K + ac);
            if (APPLY_BN) {
                v0.x = fmaxf(fmaf(v0.x, sscale[ac + 0], sshift[ac + 0]), 0.f);
                v0.y = fmaxf(fmaf(v0.y, sscale[ac + 1], sshift[ac + 1]), 0.f);
                v0.z = fmaxf(fmaf(v0.z, sscale[ac + 2], sshift[ac + 2]), 0.f);
                v0.w = fmaxf(fmaf(v0.w, sscale[ac + 3], sshift[ac + 3]), 0.f);
            }
        }
        if (gr1 < M) {
            v1 = *(const float4*)(A + (long)gr1 * K + ac);
            if (APPLY_BN) {
                v1.x = fmaxf(fmaf(v1.x, sscale[ac + 0], sshift[ac + 0]), 0.f);
                v1.y = fmaxf(fmaf(v1.y, sscale[ac + 1], sshift[ac + 1]), 0.f);
                v1.z = fmaxf(fmaf(v1.z, sscale[ac + 2], sshift[ac + 2]), 0.f);
                v1.w = fmaxf(fmaf(v1.w, sscale[ac + 3], sshift[ac + 3]), 0.f);
            }
        }
        float4 vb = *(const float4*)(B + (long)brr * N + bcol + bcc);
        As[0][ar0][ac + 0] = f2tf(v0.x); As[0][ar0][ac + 1] = f2tf(v0.y);
        As[0][ar0][ac + 2] = f2tf(v0.z); As[0][ar0][ac + 3] = f2tf(v0.w);
        As[0][ar1][ac + 0] = f2tf(v1.x); As[0][ar1][ac + 1] = f2tf(v1.y);
        As[0][ar1][ac + 2] = f2tf(v1.z); As[0][ar1][ac + 3] = f2tf(v1.w);
        Bs[0][brr][bcc + 0] = f2tf(vb.x); Bs[0][brr][bcc + 1] = f2tf(vb.y);
        Bs[0][brr][bcc + 2] = f2tf(vb.z); Bs[0][brr][bcc + 3] = f2tf(vb.w);
    }
    __syncthreads();

    for (int it = 0; it < NT; it++) {
        int cur = it & 1;
        bool hn = (it + 1) < NT;
        float4 p0 = make_float4(0.f, 0.f, 0.f, 0.f);
        float4 p1 = make_float4(0.f, 0.f, 0.f, 0.f);
        float4 pb = make_float4(0.f, 0.f, 0.f, 0.f);
        if (hn) {   // prefetch slab it+1 into registers (overlaps with MMAs below)
            int k0 = (it + 1) * 16;
            int gr0 = brow + ar0, gr1 = brow + ar1;
            if (gr0 < M) {
                p0 = *(const float4*)(A + (long)gr0 * K + k0 + ac);
                if (APPLY_BN) {
                    int c = k0 + ac;
                    p0.x = fmaxf(fmaf(p0.x, sscale[c + 0], sshift[c + 0]), 0.f);
                    p0.y = fmaxf(fmaf(p0.y, sscale[c + 1], sshift[c + 1]), 0.f);
                    p0.z = fmaxf(fmaf(p0.z, sscale[c + 2], sshift[c + 2]), 0.f);
                    p0.w = fmaxf(fmaf(p0.w, sscale[c + 3], sshift[c + 3]), 0.f);
                }
            }
            if (gr1 < M) {
                p1 = *(const float4*)(A + (long)gr1 * K + k0 + ac);
                if (APPLY_BN) {
                    int c = k0 + ac;
                    p1.x = fmaxf(fmaf(p1.x, sscale[c + 0], sshift[c + 0]), 0.f);
                    p1.y = fmaxf(fmaf(p1.y, sscale[c + 1], sshift[c + 1]), 0.f);
                    p1.z = fmaxf(fmaf(p1.z, sscale[c + 2], sshift[c + 2]), 0.f);
                    p1.w = fmaxf(fmaf(p1.w, sscale[c + 3], sshift[c + 3]), 0.f);
                }
            }
            pb = *(const float4*)(B + (long)(k0 + brr) * N + bcol + bcc);
        }

        // compute on buffer `cur`
        #pragma unroll
        for (int k8 = 0; k8 < 16; k8 += 8) {
            unsigned af[2][4], bf[4][2];
            #pragma unroll
            for (int mt = 0; mt < 2; mt++) {
                int r0 = mbase + mt * 16 + g;
                int c = k8 + tg;
                af[mt][0] = As[cur][r0][c];
                af[mt][1] = As[cur][r0 + 8][c];
                af[mt][2] = As[cur][r0][c + 4];
                af[mt][3] = As[cur][r0 + 8][c + 4];
            }
            #pragma unroll
            for (int nt = 0; nt < 4; nt++) {
                int cb = nbase + nt * 8 + g;
                int rb = k8 + tg;
                bf[nt][0] = Bs[cur][rb][cb];
                bf[nt][1] = Bs[cur][rb + 4][cb];
            }
            #pragma unroll
            for (int mt = 0; mt < 2; mt++)
                #pragma unroll
                for (int nt = 0; nt < 4; nt++) mma_tf32(acc[mt][nt], af[mt], bf[nt]);
        }

        if (hn) {   // store prefetched slab to the other buffer; safe: it was last read in it-1
            int nb = cur ^ 1;
            As[nb][ar0][ac + 0] = f2tf(p0.x); As[nb][ar0][ac + 1] = f2tf(p0.y);
            As[nb][ar0][ac + 2] = f2tf(p0.z); As[nb][ar0][ac + 3] = f2tf(p0.w);
            As[nb][ar1][ac + 0] = f2tf(p1.x); As[nb][ar1][ac + 1] = f2tf(p1.y);
            As[nb][ar1][ac + 2] = f2tf(p1.z); As[nb][ar1][ac + 3] = f2tf(p1.w);
            Bs[nb][brr][bcc + 0] = f2tf(pb.x); Bs[nb][brr][bcc + 1] = f2tf(pb.y);
            Bs[nb][brr][bcc + 2] = f2tf(pb.z); Bs[nb][brr][bcc + 3] = f2tf(pb.w);
            __syncthreads();
        }
    }

    #pragma unroll
    for (int mt = 0; mt < 2; mt++) {
        #pragma unroll
        for (int nt = 0; nt < 4; nt++) {
            int row = brow + mbase + mt * 16 + g;
            int col = bcol + nbase + nt * 8 + 2 * tg;
            if (row < M)
                *(float2*)(C + (long)row * N + col) = make_float2(acc[mt][nt].x, acc[mt][nt].y);
            if (row + 8 < M)
                *(float2*)(C + (long)(row + 8) * N + col) = make_float2(acc[mt][nt].z, acc[mt][nt].w);
        }
    }

    // fused attention-logit epilogue
    {
        int head = (2 * bcol >= N) ? 1 : 0;
        float av_s[8], av_d[8];
        #pragma unroll
        for (int nt = 0; nt < 4; nt++) {
            int col = bcol + nbase + nt * 8 + 2 * tg;
            av_s[nt * 2 + 0] = __ldg(asrc + col);
            av_s[nt * 2 + 1] = __ldg(asrc + col + 1);
            av_d[nt * 2 + 0] = __ldg(adst + col);
            av_d[nt * 2 + 1] = __ldg(adst + col + 1);
        }
        #pragma unroll
        for (int mt = 0; mt < 2; mt++) {
            float pes0 = 0.f, ped0 = 0.f, pes8 = 0.f, ped8 = 0.f;
            #pragma unroll
            for (int nt = 0; nt < 4; nt++) {
                float4 a = acc[mt][nt];
                pes0 += a.x * av_s[nt * 2] + a.y * av_s[nt * 2 + 1];
                ped0 += a.x * av_d[nt * 2] + a.y * av_d[nt * 2 + 1];
                pes8 += a.z * av_s[nt * 2] + a.w * av_s[nt * 2 + 1];
                ped8 += a.z * av_d[nt * 2] + a.w * av_d[nt * 2 + 1];
            }
            #pragma unroll
            for (int o = 1; o <= 2; o <<= 1) {
                pes0 += __shfl_xor_sync(0xffffffffu, pes0, o);
                ped0 += __shfl_xor_sync(0xffffffffu, ped0, o);
                pes8 += __shfl_xor_sync(0xffffffffu, pes8, o);
                ped8 += __shfl_xor_sync(0xffffffffu, ped8, o);
            }
            if (tg == 0) {
                int row = brow + mbase + mt * 16 + g;
                if (row < M) {
                    atomicAdd(&es[row * 2 + head], pes0);
                    atomicAdd(&ed[row * 2 + head], ped0);
                }
                if (row + 8 < M) {
                    atomicAdd(&es[(row + 8) * 2 + head], pes8);
                    atomicAdd(&ed[(row + 8) * 2 + head], ped8);
                }
            }
        }
    }
}

// ---------------- combo: gemm1 tiles + CSR fill + graph bounds ----------------
__global__ void combo1(const float* __restrict__ x, const float* __restrict__ W1,
                       float* __restrict__ h1,
                       const float* __restrict__ a_s1, const float* __restrict__ a_d1,
                       float* __restrict__ es1, float* __restrict__ ed1,
                       const int* __restrict__ esrc, const int* __restrict__ edst,
                       int* __restrict__ cursor, int* __restrict__ csrc,
                       const int* __restrict__ batch, int* __restrict__ gstart) {
    int bid = blockIdx.x;
    if (bid < GEMM1_BLOCKS) {
        gemm_body<false>(bid & 1, bid >> 1, x, W1, h1, NN, 128, 64,
                         nullptr, nullptr, nullptr, nullptr, a_s1, a_d1, es1, ed1);
    } else if (bid < GEMM1_BLOCKS + CSR_BLOCKS) {
        int idx = (bid - GEMM1_BLOCKS) * 256 + threadIdx.x;
        if (idx < EE) {
            int t = edst[idx];
            int p = atomicAdd(&cursor[t], 1);
            csrc[p] = esrc[idx];
        } else if (idx < EE + NN) {
            int n = idx - EE;
            int p = atomicAdd(&cursor[n], 1);
            csrc[p] = n;
        }
    } else {
        int g = threadIdx.x;
        if (g <= GG) {
            int lo = 0, hi = NN;
            while (lo < hi) {
                int mid = (lo + hi) >> 1;
                if (batch[mid] < g) lo = mid + 1; else hi = mid;
            }
            gstart[g] = lo;
        }
    }
}

__global__ void gemm_k(int nbx, const float* A, const float* B, float* C, int M, int N, int K,
                       const float* bs, const float* bq, const float* gamma, const float* beta,
                       const float* asrc, const float* adst, float* es, float* ed) {
    gemm_body<true>(blockIdx.x % nbx, blockIdx.x / nbx, A, B, C, M, N, K,
                    bs, bq, gamma, beta, asrc, adst, es, ed);
}

// ---------------- fused GAT: single-pass softmax (R13 best config) ----------------
#define GBODY(jj)                                                        \
    {                                                                    \
        int s_ = __shfl_sync(0xffffffffu, sreg, (jj));                   \
        float ww0_ = __shfl_sync(0xffffffffu, w0, (jj));                 \
        float ww1_ = __shfl_sync(0xffffffffu, w1, (jj));                 \
        const float* hp_ = h + (long)s_ * C;                             \
        if (C == 128) {                                                  \
            float4 hv = *(const float4*)(hp_ + lane * 4);                \
            float w_ = (lane < 16) ? ww0_ : ww1_;                        \
            acc0.x = fmaf(hv.x, w_, acc0.x);                             \
            acc0.y = fmaf(hv.y, w_, acc0.y);                             \
            acc0.z = fmaf(hv.z, w_, acc0.z);                             \
            acc0.w = fmaf(hv.w, w_, acc0.w);                             \
        } else {                                                         \
            float4 hv0 = *(const float4*)(hp_ + lane * 4);               \
            float4 hv1 = *(const float4*)(hp_ + 128 + lane * 4);         \
            acc0.x = fmaf(hv0.x, ww0_, acc0.x);                          \
            acc0.y = fmaf(hv0.y, ww0_, acc0.y);                          \
            acc0.z = fmaf(hv0.z, ww0_, acc0.z);                          \
            acc0.w = fmaf(hv0.w, ww0_, acc0.w);                          \
            acc1.x = fmaf(hv1.x, ww1_, acc1.x);                          \
            acc1.y = fmaf(hv1.y, ww1_, acc1.y);                          \
            acc1.z = fmaf(hv1.z, ww1_, acc1.z);                          \
            acc1.w = fmaf(hv1.w, ww1_, acc1.w);                          \
        }                                                                \
    }

template <int C>
__global__ __launch_bounds__(512, 3)
void fused_gat(const int* __restrict__ off, const int* __restrict__ csrc,
               const float* __restrict__ es, const float* __restrict__ ed,
               const float* __restrict__ h, const float* __restrict__ bias,
               float* __restrict__ y,
               float* __restrict__ bnsum, float* __restrict__ bnsq) {
    __shared__ float ssum[C];
    __shared__ float ssq[C];
    const int tid = threadIdx.x;
    for (int i = tid; i < C; i += 512) { ssum[i] = 0.f; ssq[i] = 0.f; }
    __syncthreads();

    int t = blockIdx.x * 16 + (tid >> 5);
    int lane = tid & 31;
    bool valid = t < NN;
    int b = 0, e = 0;
    float ed0 = 0.f, ed1 = 0.f;
    if (valid) {
        b = off[t];
        e = off[t + 1];
        ed0 = ed[t * 2];
        ed1 = ed[t * 2 + 1];
    }

    float den0 = 0.f, den1 = 0.f;
    float4 acc0 = make_float4(0.f, 0.f, 0.f, 0.f);
    float4 acc1 = make_float4(0.f, 0.f, 0.f, 0.f);
    for (int base = b; base < e; base += 32) {
        int n = min(32, e - base);
        float w0 = 0.f, w1 = 0.f;
        int sreg = 0;
        if (lane < n) {
            sreg = csrc[base + lane];
            float2 esv = *(const float2*)(es + sreg * 2);
            float v0 = esv.x + ed0; v0 = v0 > 0.f ? v0 : 0.2f * v0;
            float v1 = esv.y + ed1; v1 = v1 > 0.f ? v1 : 0.2f * v1;
            w0 = __expf(v0);
            w1 = __expf(v1);
            den0 += w0;
            den1 += w1;
        }
        if (n == 32) {
            #pragma unroll 1
            for (int j = 0; j < 32; j += 4) {
                GBODY(j)
                GBODY(j + 1)
                GBODY(j + 2)
                GBODY(j + 3)
            }
        } else {
            for (int j = 0; j < n; j++) GBODY(j)
        }
    }
    #pragma unroll
    for (int o = 16; o; o >>= 1) {
        den0 += __shfl_xor_sync(0xffffffffu, den0, o);
        den1 += __shfl_xor_sync(0xffffffffu, den1, o);
    }

    if (valid) {
        float r0 = 1.f / (den0 + 1e-16f);
        float r1 = 1.f / (den1 + 1e-16f);
        if (C == 128) {
            float r = (lane < 16) ? r0 : r1;
            int c = lane * 4;
            const float4 bb = *(const float4*)(bias + c);
            float4 o = make_float4(acc0.x * r + bb.x, acc0.y * r + bb.y,
                                   acc0.z * r + bb.z, acc0.w * r + bb.w);
            *(float4*)(y + (long)t * C + c) = o;
            atomicAdd(&ssum[c + 0], o.x); atomicAdd(&ssq[c + 0], o.x * o.x);
            atomicAdd(&ssum[c + 1], o.y); atomicAdd(&ssq[c + 1], o.y * o.y);
            atomicAdd(&ssum[c + 2], o.z); atomicAdd(&ssq[c + 2], o.z * o.z);
            atomicAdd(&ssum[c + 3], o.w); atomicAdd(&ssq[c + 3], o.w * o.w);
        } else {
            int c0 = lane * 4, c1 = 128 + lane * 4;
            const float4 b0 = *(const float4*)(bias + c0);
            const float4 b1 = *(const float4*)(bias + c1);
            float4 o0 = make_float4(acc0.x * r0 + b0.x, acc0.y * r0 + b0.y,
                                    acc0.z * r0 + b0.z, acc0.w * r0 + b0.w);
            float4 o1 = make_float4(acc1.x * r1 + b1.x, acc1.y * r1 + b1.y,
                                    acc1.z * r1 + b1.z, acc1.w * r1 + b1.w);
            *(float4*)(y + (long)t * C + c0) = o0;
            *(float4*)(y + (long)t * C + c1) = o1;
            atomicAdd(&ssum[c0 + 0], o0.x); atomicAdd(&ssq[c0 + 0], o0.x * o0.x);
            atomicAdd(&ssum[c0 + 1], o0.y); atomicAdd(&ssq[c0 + 1], o0.y * o0.y);
            atomicAdd(&ssum[c0 + 2], o0.z); atomicAdd(&ssq[c0 + 2], o0.z * o0.z);
            atomicAdd(&ssum[c0 + 3], o0.w); atomicAdd(&ssq[c0 + 3], o0.w * o0.w);
            atomicAdd(&ssum[c1 + 0], o1.x); atomicAdd(&ssq[c1 + 0], o1.x * o1.x);
            atomicAdd(&ssum[c1 + 1], o1.y); atomicAdd(&ssq[c1 + 1], o1.y * o1.y);
            atomicAdd(&ssum[c1 + 2], o1.z); atomicAdd(&ssq[c1 + 2], o1.z * o1.z);
            atomicAdd(&ssum[c1 + 3], o1.w); atomicAdd(&ssq[c1 + 3], o1.w * o1.w);
        }
    }
    __syncthreads();
    for (int i = tid; i < C; i += 512) {
        atomicAdd(&bnsum[i], ssum[i]);
        atomicAdd(&bnsq[i], ssq[i]);
    }
}

// ---------------- pooling: one block per graph; fused BN2-finalize + relu ----------------
__global__ void pool_bn(const float* __restrict__ y2, const int* __restrict__ gstart,
                        const float* __restrict__ bs, const float* __restrict__ bq,
                        const float* __restrict__ gamma, const float* __restrict__ beta,
                        float* __restrict__ pooled) {
    int c = threadIdx.x;  // 256
    float m = bs[c] / (float)NN;
    float var = bq[c] / (float)NN - m * m;
    float sc = rsqrtf(var + 1e-5f) * gamma[c];
    float sh = beta[c] - m * sc;
    int g = blockIdx.x;
    int b = gstart[g], e = gstart[g + 1];
    float s = 0.f;
    for (int r = b; r < e; r++) s += fmaxf(fmaf(y2[(long)r * 256 + c], sc, sh), 0.f);
    pooled[g * 256 + c] = s / fmaxf((float)(e - b), 1.f);
}

// ---------------- FC head ----------------
__global__ void fc_kernel(const float* __restrict__ in, const float* __restrict__ W,
                          const float* __restrict__ b, float* __restrict__ out,
                          int M, int N, int K) {
    int idx = blockIdx.x * blockDim.x + threadIdx.x;
    if (idx >= M * N) return;
    int r = idx / N, c = idx % N;
    float s = b[c];
    for (int k = 0; k < K; k++) s += in[r * K + k] * W[k * N + c];
    out[idx] = s;
}

__global__ void bn_small_relu(const float* __restrict__ in, const float* __restrict__ g,
                              const float* __restrict__ b, float* __restrict__ out, int C) {
    int c = blockIdx.x * blockDim.x + threadIdx.x;
    if (c >= C) return;
    float s = 0.f, sq = 0.f;
    for (int r = 0; r < GG; r++) {
        float v = in[r * C + c];
        s += v;
        sq += v * v;
    }
    float mu = s / (float)GG;
    float rstd = rsqrtf(sq / (float)GG - mu * mu + 1e-5f);
    for (int r = 0; r < GG; r++) {
        float v = (in[r * C + c] - mu) * rstd * g[c] + b[c];
        out[r * C + c] = fmaxf(v, 0.f);
    }
}

// BN over z2 + final linear, single block
__global__ void bn2_final(const float* __restrict__ z2, const float* __restrict__ g2,
                          const float* __restrict__ b2, const float* __restrict__ Wout,
                          const float* __restrict__ bout, float* __restrict__ z2n,
                          float* __restrict__ out) {
    int c = threadIdx.x;  // 256
    float s = 0.f, sq = 0.f;
    for (int r = 0; r < GG; r++) {
        float v = z2[r * 256 + c];
        s += v;
        sq += v * v;
    }
    float mu = s / (float)GG;
    float rstd = rsqrtf(sq / (float)GG - mu * mu + 1e-5f);
    for (int r = 0; r < GG; r++) {
        float v = (z2[r * 256 + c] - mu) * rstd * g2[c] + b2[c];
        z2n[r * 256 + c] = fmaxf(v, 0.f);
    }
    __syncthreads();
    if (c < GG) {
        float acc = bout[0];
        for (int k = 0; k < 256; k++) acc += z2n[c * 256 + k] * Wout[k];
        out[c] = acc;
    }
}

// ---------------- tail cleanup ----------------
__global__ void cleanup(int* __restrict__ deg, float* __restrict__ es1, float* __restrict__ ed1,
                        float* __restrict__ es2, float* __restrict__ ed2,
                        float* __restrict__ bs1, float* __restrict__ bq1,
                        float* __restrict__ bs2, float* __restrict__ bq2) {
    int i = blockIdx.x * blockDim.x + threadIdx.x;
    if (i < NN) deg[i] = 0;
    if (i < NN * 2) { es1[i] = 0.f; ed1[i] = 0.f; es2[i] = 0.f; ed2[i] = 0.f; }
    if (i < 128) { bs1[i] = 0.f; bq1[i] = 0.f; }
    if (i < 256) { bs2[i] = 0.f; bq2[i] = 0.f; }
}

// ---------------- host driver ----------------
static inline int cdiv(long a, int b) { return (int)((a + b - 1) / b); }

extern "C" void kernel_launch(void* const* d_in, const int* in_sizes, int n_in,
                              void* d_out, int out_size) {
    const float* x    = (const float*)d_in[0];
    const int*   esrc = (const int*)d_in[1];
    const int*   edst = (const int*)d_in[2];
    const int*   batch= (const int*)d_in[3];
    const float* W1   = (const float*)d_in[4];
    const float* a_s1 = (const float*)d_in[5];
    const float* a_d1 = (const float*)d_in[6];
    const float* b1   = (const float*)d_in[7];
    const float* g1   = (const float*)d_in[8];
    const float* be1  = (const float*)d_in[9];
    const float* W2   = (const float*)d_in[10];
    const float* a_s2 = (const float*)d_in[11];
    const float* a_d2 = (const float*)d_in[12];
    const float* b2   = (const float*)d_in[13];
    const float* g2   = (const float*)d_in[14];
    const float* be2  = (const float*)d_in[15];
    const float* Wf1  = (const float*)d_in[16];
    const float* bf1  = (const float*)d_in[17];
    const float* gf1  = (const float*)d_in[18];
    const float* bef1 = (const float*)d_in[19];
    const float* Wf2  = (const float*)d_in[20];
    const float* bf2  = (const float*)d_in[21];
    const float* gf2  = (const float*)d_in[22];
    const float* bef2 = (const float*)d_in[23];
    const float* Wout = (const float*)d_in[24];
    const float* bout = (const float*)d_in[25];
    float* out = (float*)d_out;

    float *h1, *y1, *h2, *y2, *es1, *ed1, *es2, *ed2;
    int *deg, *off, *cursor, *csrc, *gstart;
    float *bs1, *bq1, *bs2, *bq2, *pooled, *z1, *z1n, *z2, *z2n;
    cudaGetSymbolAddress((void**)&h1, d_h1);
    cudaGetSymbolAddress((void**)&y1, d_y1);
    cudaGetSymbolAddress((void**)&h2, d_h2);
    cudaGetSymbolAddress((void**)&y2, d_y2);
    cudaGetSymbolAddress((void**)&es1, d_es1);
    cudaGetSymbolAddress((void**)&ed1, d_ed1);
    cudaGetSymbolAddress((void**)&es2, d_es2);
    cudaGetSymbolAddress((void**)&ed2, d_ed2);
    cudaGetSymbolAddress((void**)&deg, d_deg);
    cudaGetSymbolAddress((void**)&off, d_off);
    cudaGetSymbolAddress((void**)&cursor, d_cursor);
    cudaGetSymbolAddress((void**)&csrc, d_csrc);
    cudaGetSymbolAddress((void**)&gstart, d_gstart);
    cudaGetSymbolAddress((void**)&bs1, d_bs1);
    cudaGetSymbolAddress((void**)&bq1, d_bq1);
    cudaGetSymbolAddress((void**)&bs2, d_bs2);
    cudaGetSymbolAddress((void**)&bq2, d_bq2);
    cudaGetSymbolAddress((void**)&pooled, d_pooled);
    cudaGetSymbolAddress((void**)&z1, d_z1);
    cudaGetSymbolAddress((void**)&z1n, d_z1n);
    cudaGetSymbolAddress((void**)&z2, d_z2);
    cudaGetSymbolAddress((void**)&z2n, d_z2n);

    const int TB = 256;

    // 1: degree count
    count_deg<<<cdiv(EE, TB), TB>>>(edst, deg);
    // 2: offsets scan (+1 self-loop folded in)
    scan_offsets<<<1, 1024>>>(deg, off, cursor);
    // 3: gemm1 + CSR fill + graph bounds
    combo1<<<GEMM1_BLOCKS + CSR_BLOCKS + 1, 256>>>(x, W1, h1, a_s1, a_d1, es1, ed1,
                                                   esrc, edst, cursor, csrc, batch, gstart);
    // 4: fused GAT layer 1  (ncu window)
    fused_gat<128><<<cdiv(NN, 16), 512>>>(off, csrc, es1, ed1, h1, b1, y1, bs1, bq1);
    // 5: gemm2 (BN1 finalize+apply fused)
    gemm_k<<<4 * cdiv(NN, 128), 256>>>(4, y1, W2, h2, NN, 256, 128,
                                       bs1, bq1, g1, be1, a_s2, a_d2, es2, ed2);
    // 6: fused GAT layer 2
    fused_gat<256><<<cdiv(NN, 16), 512>>>(off, csrc, es2, ed2, h2, b2, y2, bs2, bq2);
    // 7: pool (BN2 finalize+relu fused)
    pool_bn<<<GG, 256>>>(y2, gstart, bs2, bq2, g2, be2, pooled);
    // 8-11: FC head
    fc_kernel<<<cdiv(GG * 512, TB), TB>>>(pooled, Wf1, bf1, z1, GG, 512, 256);
    bn_small_relu<<<2, 256>>>(z1, gf1, bef1, z1n, 512);
    fc_kernel<<<cdiv(GG * 256, TB), TB>>>(z1n, Wf2, bf2, z2, GG, 256, 512);
    bn2_final<<<1, 256>>>(z2, gf2, bef2, Wout, bout, z2n, out);
    // 12: tail cleanup for next replay
    cleanup<<<cdiv(NN * 2, TB), TB>>>(deg, es1, ed1, es2, ed2, bs1, bq1, bs2, bq2);
}

// round 17
// speedup vs baseline: 1.1919x; 1.1746x over previous
#include <cuda_runtime.h>
#include <cuda_bf16.h>

#define NN 50000
#define EE 500000
#define HH 2
#define GG 128
#define NB_SCAN ((NN + 255) / 256)   // 196

// ---------------- scratch ----------------
__device__ float d_h1[NN * 128];
__device__ float d_y1[NN * 128];
__device__ float d_h2[NN * 256];
__device__ float d_y2[NN * 256];
__device__ float d_es1[NN * 2], d_ed1[NN * 2];
__device__ float d_es2[NN * 2], d_ed2[NN * 2];
__device__ int   d_deg[NN], d_off[NN + 1], d_cursor[NN];
__device__ int   d_part[256];
__device__ int   d_csrc[EE + NN];
__device__ int   d_gstart[GG + 1];
__device__ float d_bs1[128], d_bq1[128];
__device__ float d_bs2[256], d_bq2[256];
__device__ float d_pooled[GG * 256];
__device__ float d_z1[GG * 512], d_z1n[GG * 512];
__device__ float d_z2[GG * 256], d_z2n[GG * 256];

static const int GEMM1_BLOCKS = 2 * ((NN + 127) / 128);            // 782
static const int CSR_BLOCKS = (EE + NN + 255) / 256;               // 2149

// ---------------- CSR: degree count ----------------
__global__ void count_deg(const int* __restrict__ dst, int* __restrict__ deg) {
    int e = blockIdx.x * blockDim.x + threadIdx.x;
    if (e < EE) atomicAdd(&deg[dst[e]], 1);
}

// ---------------- parallel 3-phase scan (degree = deg[i]+1, implicit self-loop) ----------------
__global__ void scan_part(const int* __restrict__ deg, int* __restrict__ part) {
    __shared__ int sm[256];
    int idx = blockIdx.x * 256 + threadIdx.x;
    sm[threadIdx.x] = (idx < NN) ? deg[idx] + 1 : 0;
    __syncthreads();
    for (int d = 128; d; d >>= 1) {
        if (threadIdx.x < d) sm[threadIdx.x] += sm[threadIdx.x + d];
        __syncthreads();
    }
    if (threadIdx.x == 0) part[blockIdx.x] = sm[0];
}

__global__ void scan_top(int* __restrict__ part) {
    __shared__ int sm[256];
    int t = threadIdx.x;
    int v = (t < NB_SCAN) ? part[t] : 0;
    sm[t] = v;
    __syncthreads();
    for (int d = 1; d < 256; d <<= 1) {
        int u = (t >= d) ? sm[t - d] : 0;
        __syncthreads();
        sm[t] += u;
        __syncthreads();
    }
    if (t < NB_SCAN) part[t] = sm[t] - v;   // exclusive
}

__global__ void scan_write(const int* __restrict__ deg, const int* __restrict__ part,
                           int* __restrict__ off, int* __restrict__ cursor) {
    __shared__ int sm[256];
    int b = blockIdx.x;
    int idx = b * 256 + threadIdx.x;
    int v = (idx < NN) ? deg[idx] + 1 : 0;
    sm[threadIdx.x] = v;
    __syncthreads();
    for (int d = 1; d < 256; d <<= 1) {
        int u = (threadIdx.x >= d) ? sm[threadIdx.x - d] : 0;
        __syncthreads();
        sm[threadIdx.x] += u;
        __syncthreads();
    }
    if (idx < NN) {
        int excl = part[b] + sm[threadIdx.x] - v;
        off[idx] = excl;
        cursor[idx] = excl;
        if (idx == NN - 1) off[NN] = excl + v;
    }
}

// ---------------- tf32 GEMM body: double-buffered smem, 1 sync per K-slab ----------------
__device__ __forceinline__ unsigned f2tf(float f) {
    unsigned r;
    asm("cvt.rna.tf32.f32 %0, %1;" : "=r"(r) : "f"(f));
    return r;
}
__device__ __forceinline__ void mma_tf32(float4& c, const unsigned* a, const unsigned* b) {
    asm volatile(
        "mma.sync.aligned.m16n8k8.row.col.f32.tf32.tf32.f32 "
        "{%0,%1,%2,%3}, {%4,%5,%6,%7}, {%8,%9}, {%0,%1,%2,%3};"
        : "+f"(c.x), "+f"(c.y), "+f"(c.z), "+f"(c.w)
        : "r"(a[0]), "r"(a[1]), "r"(a[2]), "r"(a[3]), "r"(b[0]), "r"(b[1]));
}

template <bool APPLY_BN>
__device__ void gemm_body(int bx, int by,
                          const float* __restrict__ A, const float* __restrict__ B,
                          float* __restrict__ C, int M, int N, int K,
                          const float* __restrict__ bs, const float* __restrict__ bq,
                          const float* __restrict__ gamma, const float* __restrict__ beta,
                          const float* __restrict__ asrc, const float* __restrict__ adst,
                          float* __restrict__ es, float* __restrict__ ed) {
    __shared__ unsigned As[2][128][17];
    __shared__ unsigned Bs[2][16][72];
    __shared__ float sscale[128], sshift[128];
    const int brow = by * 128;
    const int bcol = bx * 64;
    const int tid = threadIdx.x;
    const int w = tid >> 5, l = tid & 31;
    const int wm = w & 3, wn = w >> 2;
    const int mbase = wm * 32, nbase = wn * 32;
    const int g = l >> 2, tg = l & 3;

    const int ar0 = tid >> 2;
    const int ar1 = ar0 + 64;
    const int ac = (tid & 3) * 4;
    const int brr = tid >> 4;
    const int bcc = (tid & 15) * 4;

    if (APPLY_BN) {
        if (tid < K) {
            float m = bs[tid] / (float)NN;
            float var = bq[tid] / (float)NN - m * m;
            float sc = rsqrtf(var + 1e-5f) * gamma[tid];
            sscale[tid] = sc;
            sshift[tid] = beta[tid] - m * sc;
        }
        __syncthreads();
    }

    float4 acc[2][4];
    #pragma unroll
    for (int i = 0; i < 2; i++)
        #pragma unroll
        for (int j = 0; j < 4; j++) acc[i][j] = make_float4(0.f, 0.f, 0.f, 0.f);

    const int NT = K / 16;

    {
        float4 v0 = make_float4(0.f, 0.f, 0.f, 0.f);
        float4 v1 = make_float4(0.f, 0.f, 0.f, 0.f);
        int gr0 = brow + ar0, gr1 = brow + ar1;
        if (gr0 < M) {
            v0 = *(const float4*)(A + (long)gr0 * K + ac);
            if (APPLY_BN) {
                v0.x = fmaxf(fmaf(v0.x, sscale[ac + 0], sshift[ac + 0]), 0.f);
                v0.y = fmaxf(fmaf(v0.y, sscale[ac + 1], sshift[ac + 1]), 0.f);
                v0.z = fmaxf(fmaf(v0.z, sscale[ac + 2], sshift[ac + 2]), 0.f);
                v0.w = fmaxf(fmaf(v0.w, sscale[ac + 3], sshift[ac + 3]), 0.f);
            }
        }
        if (gr1 < M) {
            v1 = *(const float4*)(A + (long)gr1 * K + ac);
            if (APPLY_BN) {
                v1.x = fmaxf(fmaf(v1.x, sscale[ac + 0], sshift[ac + 0]), 0.f);
                v1.y = fmaxf(fmaf(v1.y, sscale[ac + 1], sshift[ac + 1]), 0.f);
                v1.z = fmaxf(fmaf(v1.z, sscale[ac + 2], sshift[ac + 2]), 0.f);
                v1.w = fmaxf(fmaf(v1.w, sscale[ac + 3], sshift[ac + 3]), 0.f);
            }
        }
        float4 vb = *(const float4*)(B + (long)brr * N + bcol + bcc);
        As[0][ar0][ac + 0] = f2tf(v0.x); As[0][ar0][ac + 1] = f2tf(v0.y);
        As[0][ar0][ac + 2] = f2tf(v0.z); As[0][ar0][ac + 3] = f2tf(v0.w);
        As[0][ar1][ac + 0] = f2tf(v1.x); As[0][ar1][ac + 1] = f2tf(v1.y);
        As[0][ar1][ac + 2] = f2tf(v1.z); As[0][ar1][ac + 3] = f2tf(v1.w);
        Bs[0][brr][bcc + 0] = f2tf(vb.x); Bs[0][brr][bcc + 1] = f2tf(vb.y);
        Bs[0][brr][bcc + 2] = f2tf(vb.z); Bs[0][brr][bcc + 3] = f2tf(vb.w);
    }
    __syncthreads();

    for (int it = 0; it < NT; it++) {
        int cur = it & 1;
        bool hn = (it + 1) < NT;
        float4 p0 = make_float4(0.f, 0.f, 0.f, 0.f);
        float4 p1 = make_float4(0.f, 0.f, 0.f, 0.f);
        float4 pb = make_float4(0.f, 0.f, 0.f, 0.f);
        if (hn) {
            int k0 = (it + 1) * 16;
            int gr0 = brow + ar0, gr1 = brow + ar1;
            if (gr0 < M) {
                p0 = *(const float4*)(A + (long)gr0 * K + k0 + ac);
                if (APPLY_BN) {
                    int c = k0 + ac;
                    p0.x = fmaxf(fmaf(p0.x, sscale[c + 0], sshift[c + 0]), 0.f);
                    p0.y = fmaxf(fmaf(p0.y, sscale[c + 1], sshift[c + 1]), 0.f);
                    p0.z = fmaxf(fmaf(p0.z, sscale[c + 2], sshift[c + 2]), 0.f);
                    p0.w = fmaxf(fmaf(p0.w, sscale[c + 3], sshift[c + 3]), 0.f);
                }
            }
            if (gr1 < M) {
                p1 = *(const float4*)(A + (long)gr1 * K + k0 + ac);
                if (APPLY_BN) {
                    int c = k0 + ac;
                    p1.x = fmaxf(fmaf(p1.x, sscale[c + 0], sshift[c + 0]), 0.f);
                    p1.y = fmaxf(fmaf(p1.y, sscale[c + 1], sshift[c + 1]), 0.f);
                    p1.z = fmaxf(fmaf(p1.z, sscale[c + 2], sshift[c + 2]), 0.f);
                    p1.w = fmaxf(fmaf(p1.w, sscale[c + 3], sshift[c + 3]), 0.f);
                }
            }
            pb = *(const float4*)(B + (long)(k0 + brr) * N + bcol + bcc);
        }

        #pragma unroll
        for (int k8 = 0; k8 < 16; k8 += 8) {
            unsigned af[2][4], bf[4][2];
            #pragma unroll
            for (int mt = 0; mt < 2; mt++) {
                int r0 = mbase + mt * 16 + g;
                int c = k8 + tg;
                af[mt][0] = As[cur][r0][c];
                af[mt][1] = As[cur][r0 + 8][c];
                af[mt][2] = As[cur][r0][c + 4];
                af[mt][3] = As[cur][r0 + 8][c + 4];
            }
            #pragma unroll
            for (int nt = 0; nt < 4; nt++) {
                int cb = nbase + nt * 8 + g;
                int rb = k8 + tg;
                bf[nt][0] = Bs[cur][rb][cb];
                bf[nt][1] = Bs[cur][rb + 4][cb];
            }
            #pragma unroll
            for (int mt = 0; mt < 2; mt++)
                #pragma unroll
                for (int nt = 0; nt < 4; nt++) mma_tf32(acc[mt][nt], af[mt], bf[nt]);
        }

        if (hn) {
            int nb = cur ^ 1;
            As[nb][ar0][ac + 0] = f2tf(p0.x); As[nb][ar0][ac + 1] = f2tf(p0.y);
            As[nb][ar0][ac + 2] = f2tf(p0.z); As[nb][ar0][ac + 3] = f2tf(p0.w);
            As[nb][ar1][ac + 0] = f2tf(p1.x); As[nb][ar1][ac + 1] = f2tf(p1.y);
            As[nb][ar1][ac + 2] = f2tf(p1.z); As[nb][ar1][ac + 3] = f2tf(p1.w);
            Bs[nb][brr][bcc + 0] = f2tf(pb.x); Bs[nb][brr][bcc + 1] = f2tf(pb.y);
            Bs[nb][brr][bcc + 2] = f2tf(pb.z); Bs[nb][brr][bcc + 3] = f2tf(pb.w);
            __syncthreads();
        }
    }

    #pragma unroll
    for (int mt = 0; mt < 2; mt++) {
        #pragma unroll
        for (int nt = 0; nt < 4; nt++) {
            int row = brow + mbase + mt * 16 + g;
            int col = bcol + nbase + nt * 8 + 2 * tg;
            if (row < M)
                *(float2*)(C + (long)row * N + col) = make_float2(acc[mt][nt].x, acc[mt][nt].y);
            if (row + 8 < M)
                *(float2*)(C + (long)(row + 8) * N + col) = make_float2(acc[mt][nt].z, acc[mt][nt].w);
        }
    }

    // fused attention-logit epilogue
    {
        int head = (2 * bcol >= N) ? 1 : 0;
        float av_s[8], av_d[8];
        #pragma unroll
        for (int nt = 0; nt < 4; nt++) {
            int col = bcol + nbase + nt * 8 + 2 * tg;
            av_s[nt * 2 + 0] = __ldg(asrc + col);
            av_s[nt * 2 + 1] = __ldg(asrc + col + 1);
            av_d[nt * 2 + 0] = __ldg(adst + col);
            av_d[nt * 2 + 1] = __ldg(adst + col + 1);
        }
        #pragma unroll
        for (int mt = 0; mt < 2; mt++) {
            float pes0 = 0.f, ped0 = 0.f, pes8 = 0.f, ped8 = 0.f;
            #pragma unroll
            for (int nt = 0; nt < 4; nt++) {
                float4 a = acc[mt][nt];
                pes0 += a.x * av_s[nt * 2] + a.y * av_s[nt * 2 + 1];
                ped0 += a.x * av_d[nt * 2] + a.y * av_d[nt * 2 + 1];
                pes8 += a.z * av_s[nt * 2] + a.w * av_s[nt * 2 + 1];
                ped8 += a.z * av_d[nt * 2] + a.w * av_d[nt * 2 + 1];
            }
            #pragma unroll
            for (int o = 1; o <= 2; o <<= 1) {
                pes0 += __shfl_xor_sync(0xffffffffu, pes0, o);
                ped0 += __shfl_xor_sync(0xffffffffu, ped0, o);
                pes8 += __shfl_xor_sync(0xffffffffu, pes8, o);
                ped8 += __shfl_xor_sync(0xffffffffu, ped8, o);
            }
            if (tg == 0) {
                int row = brow + mbase + mt * 16 + g;
                if (row < M) {
                    atomicAdd(&es[row * 2 + head], pes0);
                    atomicAdd(&ed[row * 2 + head], ped0);
                }
                if (row + 8 < M) {
                    atomicAdd(&es[(row + 8) * 2 + head], pes8);
                    atomicAdd(&ed[(row + 8) * 2 + head], ped8);
                }
            }
        }
    }
}

// ---------------- combo: gemm1 tiles + CSR fill + graph bounds ----------------
__global__ void combo1(const float* __restrict__ x, const float* __restrict__ W1,
                       float* __restrict__ h1,
                       const float* __restrict__ a_s1, const float* __restrict__ a_d1,
                       float* __restrict__ es1, float* __restrict__ ed1,
                       const int* __restrict__ esrc, const int* __restrict__ edst,
                       int* __restrict__ cursor, int* __restrict__ csrc,
                       const int* __restrict__ batch, int* __restrict__ gstart) {
    int bid = blockIdx.x;
    if (bid < GEMM1_BLOCKS) {
        gemm_body<false>(bid & 1, bid >> 1, x, W1, h1, NN, 128, 64,
                         nullptr, nullptr, nullptr, nullptr, a_s1, a_d1, es1, ed1);
    } else if (bid < GEMM1_BLOCKS + CSR_BLOCKS) {
        int idx = (bid - GEMM1_BLOCKS) * 256 + threadIdx.x;
        if (idx < EE) {
            int t = edst[idx];
            int p = atomicAdd(&cursor[t], 1);
            csrc[p] = esrc[idx];
        } else if (idx < EE + NN) {
            int n = idx - EE;
            int p = atomicAdd(&cursor[n], 1);
            csrc[p] = n;
        }
    } else {
        int g = threadIdx.x;
        if (g <= GG) {
            int lo = 0, hi = NN;
            while (lo < hi) {
                int mid = (lo + hi) >> 1;
                if (batch[mid] < g) lo = mid + 1; else hi = mid;
            }
            gstart[g] = lo;
        }
    }
}

__global__ void gemm_k(int nbx, const float* A, const float* B, float* C, int M, int N, int K,
                       const float* bs, const float* bq, const float* gamma, const float* beta,
                       const float* asrc, const float* adst, float* es, float* ed) {
    gemm_body<true>(blockIdx.x % nbx, blockIdx.x / nbx, A, B, C, M, N, K,
                    bs, bq, gamma, beta, asrc, adst, es, ed);
}

// ---------------- fused GAT: single-pass softmax (R13 best config) ----------------
#define GBODY(jj)                                                        \
    {                                                                    \
        int s_ = __shfl_sync(0xffffffffu, sreg, (jj));                   \
        float ww0_ = __shfl_sync(0xffffffffu, w0, (jj));                 \
        float ww1_ = __shfl_sync(0xffffffffu, w1, (jj));                 \
        const float* hp_ = h + (long)s_ * C;                             \
        if (C == 128) {                                                  \
            float4 hv = *(const float4*)(hp_ + lane * 4);                \
            float w_ = (lane < 16) ? ww0_ : ww1_;                        \
            acc0.x = fmaf(hv.x, w_, acc0.x);                             \
            acc0.y = fmaf(hv.y, w_, acc0.y);                             \
            acc0.z = fmaf(hv.z, w_, acc0.z);                             \
            acc0.w = fmaf(hv.w, w_, acc0.w);                             \
        } else {                                                         \
            float4 hv0 = *(const float4*)(hp_ + lane * 4);               \
            float4 hv1 = *(const float4*)(hp_ + 128 + lane * 4);         \
            acc0.x = fmaf(hv0.x, ww0_, acc0.x);                          \
            acc0.y = fmaf(hv0.y, ww0_, acc0.y);                          \
            acc0.z = fmaf(hv0.z, ww0_, acc0.z);                          \
            acc0.w = fmaf(hv0.w, ww0_, acc0.w);                          \
            acc1.x = fmaf(hv1.x, ww1_, acc1.x);                          \
            acc1.y = fmaf(hv1.y, ww1_, acc1.y);                          \
            acc1.z = fmaf(hv1.z, ww1_, acc1.z);                          \
            acc1.w = fmaf(hv1.w, ww1_, acc1.w);                          \
        }                                                                \
    }

template <int C>
__global__ __launch_bounds__(512, 3)
void fused_gat(const int* __restrict__ off, const int* __restrict__ csrc,
               const float* __restrict__ es, const float* __restrict__ ed,
               const float* __restrict__ h, const float* __restrict__ bias,
               float* __restrict__ y,
               float* __restrict__ bnsum, float* __restrict__ bnsq) {
    __shared__ float ssum[C];
    __shared__ float ssq[C];
    const int tid = threadIdx.x;
    for (int i = tid; i < C; i += 512) { ssum[i] = 0.f; ssq[i] = 0.f; }
    __syncthreads();

    int t = blockIdx.x * 16 + (tid >> 5);
    int lane = tid & 31;
    bool valid = t < NN;
    int b = 0, e = 0;
    float ed0 = 0.f, ed1 = 0.f;
    if (valid) {
        b = off[t];
        e = off[t + 1];
        ed0 = ed[t * 2];
        ed1 = ed[t * 2 + 1];
    }

    float den0 = 0.f, den1 = 0.f;
    float4 acc0 = make_float4(0.f, 0.f, 0.f, 0.f);
    float4 acc1 = make_float4(0.f, 0.f, 0.f, 0.f);
    for (int base = b; base < e; base += 32) {
        int n = min(32, e - base);
        float w0 = 0.f, w1 = 0.f;
        int sreg = 0;
        if (lane < n) {
            sreg = csrc[base + lane];
            float2 esv = *(const float2*)(es + sreg * 2);
            float v0 = esv.x + ed0; v0 = v0 > 0.f ? v0 : 0.2f * v0;
            float v1 = esv.y + ed1; v1 = v1 > 0.f ? v1 : 0.2f * v1;
            w0 = __expf(v0);
            w1 = __expf(v1);
            den0 += w0;
            den1 += w1;
        }
        if (n == 32) {
            #pragma unroll 1
            for (int j = 0; j < 32; j += 4) {
                GBODY(j)
                GBODY(j + 1)
                GBODY(j + 2)
                GBODY(j + 3)
            }
        } else {
            for (int j = 0; j < n; j++) GBODY(j)
        }
    }
    #pragma unroll
    for (int o = 16; o; o >>= 1) {
        den0 += __shfl_xor_sync(0xffffffffu, den0, o);
        den1 += __shfl_xor_sync(0xffffffffu, den1, o);
    }

    if (valid) {
        float r0 = 1.f / (den0 + 1e-16f);
        float r1 = 1.f / (den1 + 1e-16f);
        if (C == 128) {
            float r = (lane < 16) ? r0 : r1;
            int c = lane * 4;
            const float4 bb = *(const float4*)(bias + c);
            float4 o = make_float4(acc0.x * r + bb.x, acc0.y * r + bb.y,
                                   acc0.z * r + bb.z, acc0.w * r + bb.w);
            *(float4*)(y + (long)t * C + c) = o;
            atomicAdd(&ssum[c + 0], o.x); atomicAdd(&ssq[c + 0], o.x * o.x);
            atomicAdd(&ssum[c + 1], o.y); atomicAdd(&ssq[c + 1], o.y * o.y);
            atomicAdd(&ssum[c + 2], o.z); atomicAdd(&ssq[c + 2], o.z * o.z);
            atomicAdd(&ssum[c + 3], o.w); atomicAdd(&ssq[c + 3], o.w * o.w);
        } else {
            int c0 = lane * 4, c1 = 128 + lane * 4;
            const float4 b0 = *(const float4*)(bias + c0);
            const float4 b1 = *(const float4*)(bias + c1);
            float4 o0 = make_float4(acc0.x * r0 + b0.x, acc0.y * r0 + b0.y,
                                    acc0.z * r0 + b0.z, acc0.w * r0 + b0.w);
            float4 o1 = make_float4(acc1.x * r1 + b1.x, acc1.y * r1 + b1.y,
                                    acc1.z * r1 + b1.z, acc1.w * r1 + b1.w);
            *(float4*)(y + (long)t * C + c0) = o0;
            *(float4*)(y + (long)t * C + c1) = o1;
            atomicAdd(&ssum[c0 + 0], o0.x); atomicAdd(&ssq[c0 + 0], o0.x * o0.x);
            atomicAdd(&ssum[c0 + 1], o0.y); atomicAdd(&ssq[c0 + 1], o0.y * o0.y);
            atomicAdd(&ssum[c0 + 2], o0.z); atomicAdd(&ssq[c0 + 2], o0.z * o0.z);
            atomicAdd(&ssum[c0 + 3], o0.w); atomicAdd(&ssq[c0 + 3], o0.w * o0.w);
            atomicAdd(&ssum[c1 + 0], o1.x); atomicAdd(&ssq[c1 + 0], o1.x * o1.x);
            atomicAdd(&ssum[c1 + 1], o1.y); atomicAdd(&ssq[c1 + 1], o1.y * o1.y);
            atomicAdd(&ssum[c1 + 2], o1.z); atomicAdd(&ssq[c1 + 2], o1.z * o1.z);
            atomicAdd(&ssum[c1 + 3], o1.w); atomicAdd(&ssq[c1 + 3], o1.w * o1.w);
        }
    }
    __syncthreads();
    for (int i = tid; i < C; i += 512) {
        atomicAdd(&bnsum[i], ssum[i]);
        atomicAdd(&bnsq[i], ssq[i]);
    }
}

// ---------------- pooling: one block per graph; fused BN2-finalize + relu ----------------
__global__ void pool_bn(const float* __restrict__ y2, const int* __restrict__ gstart,
                        const float* __restrict__ bs, const float* __restrict__ bq,
                        const float* __restrict__ gamma, const float* __restrict__ beta,
                        float* __restrict__ pooled) {
    int c = threadIdx.x;  // 256
    float m = bs[c] / (float)NN;
    float var = bq[c] / (float)NN - m * m;
    float sc = rsqrtf(var + 1e-5f) * gamma[c];
    float sh = beta[c] - m * sc;
    int g = blockIdx.x;
    int b = gstart[g], e = gstart[g + 1];
    float s = 0.f;
    for (int r = b; r < e; r++) s += fmaxf(fmaf(y2[(long)r * 256 + c], sc, sh), 0.f);
    pooled[g * 256 + c] = s / fmaxf((float)(e - b), 1.f);
}

// ---------------- FC head ----------------
__global__ void fc_kernel(const float* __restrict__ in, const float* __restrict__ W,
                          const float* __restrict__ b, float* __restrict__ out,
                          int M, int N, int K) {
    int idx = blockIdx.x * blockDim.x + threadIdx.x;
    if (idx >= M * N) return;
    int r = idx / N, c = idx % N;
    float s = b[c];
    for (int k = 0; k < K; k++) s += in[r * K + k] * W[k * N + c];
    out[idx] = s;
}

__global__ void bn_small_relu(const float* __restrict__ in, const float* __restrict__ g,
                              const float* __restrict__ b, float* __restrict__ out, int C) {
    int c = blockIdx.x * blockDim.x + threadIdx.x;
    if (c >= C) return;
    float s = 0.f, sq = 0.f;
    for (int r = 0; r < GG; r++) {
        float v = in[r * C + c];
        s += v;
        sq += v * v;
    }
    float mu = s / (float)GG;
    float rstd = rsqrtf(sq / (float)GG - mu * mu + 1e-5f);
    for (int r = 0; r < GG; r++) {
        float v = (in[r * C + c] - mu) * rstd * g[c] + b[c];
        out[r * C + c] = fmaxf(v, 0.f);
    }
}

// BN over z2 + final linear, single block
__global__ void bn2_final(const float* __restrict__ z2, const float* __restrict__ g2,
                          const float* __restrict__ b2, const float* __restrict__ Wout,
                          const float* __restrict__ bout, float* __restrict__ z2n,
                          float* __restrict__ out) {
    int c = threadIdx.x;  // 256
    float s = 0.f, sq = 0.f;
    for (int r = 0; r < GG; r++) {
        float v = z2[r * 256 + c];
        s += v;
        sq += v * v;
    }
    float mu = s / (float)GG;
    float rstd = rsqrtf(sq / (float)GG - mu * mu + 1e-5f);
    for (int r = 0; r < GG; r++) {
        float v = (z2[r * 256 + c] - mu) * rstd * g2[c] + b2[c];
        z2n[r * 256 + c] = fmaxf(v, 0.f);
    }
    __syncthreads();
    if (c < GG) {
        float acc = bout[0];
        for (int k = 0; k < 256; k++) acc += z2n[c * 256 + k] * Wout[k];
        out[c] = acc;
    }
}

// ---------------- tail cleanup ----------------
__global__ void cleanup(int* __restrict__ deg, float* __restrict__ es1, float* __restrict__ ed1,
                        float* __restrict__ es2, float* __restrict__ ed2,
                        float* __restrict__ bs1, float* __restrict__ bq1,
                        float* __restrict__ bs2, float* __restrict__ bq2) {
    int i = blockIdx.x * blockDim.x + threadIdx.x;
    if (i < NN) deg[i] = 0;
    if (i < NN * 2) { es1[i] = 0.f; ed1[i] = 0.f; es2[i] = 0.f; ed2[i] = 0.f; }
    if (i < 128) { bs1[i] = 0.f; bq1[i] = 0.f; }
    if (i < 256) { bs2[i] = 0.f; bq2[i] = 0.f; }
}

// ---------------- host driver ----------------
static inline int cdiv(long a, int b) { return (int)((a + b - 1) / b); }

extern "C" void kernel_launch(void* const* d_in, const int* in_sizes, int n_in,
                              void* d_out, int out_size) {
    const float* x    = (const float*)d_in[0];
    const int*   esrc = (const int*)d_in[1];
    const int*   edst = (const int*)d_in[2];
    const int*   batch= (const int*)d_in[3];
    const float* W1   = (const float*)d_in[4];
    const float* a_s1 = (const float*)d_in[5];
    const float* a_d1 = (const float*)d_in[6];
    const float* b1   = (const float*)d_in[7];
    const float* g1   = (const float*)d_in[8];
    const float* be1  = (const float*)d_in[9];
    const float* W2   = (const float*)d_in[10];
    const float* a_s2 = (const float*)d_in[11];
    const float* a_d2 = (const float*)d_in[12];
    const float* b2   = (const float*)d_in[13];
    const float* g2   = (const float*)d_in[14];
    const float* be2  = (const float*)d_in[15];
    const float* Wf1  = (const float*)d_in[16];
    const float* bf1  = (const float*)d_in[17];
    const float* gf1  = (const float*)d_in[18];
    const float* bef1 = (const float*)d_in[19];
    const float* Wf2  = (const float*)d_in[20];
    const float* bf2  = (const float*)d_in[21];
    const float* gf2  = (const float*)d_in[22];
    const float* bef2 = (const float*)d_in[23];
    const float* Wout = (const float*)d_in[24];
    const float* bout = (const float*)d_in[25];
    float* out = (float*)d_out;

    float *h1, *y1, *h2, *y2, *es1, *ed1, *es2, *ed2;
    int *deg, *off, *cursor, *part, *csrc, *gstart;
    float *bs1, *bq1, *bs2, *bq2, *pooled, *z1, *z1n, *z2, *z2n;
    cudaGetSymbolAddress((void**)&h1, d_h1);
    cudaGetSymbolAddress((void**)&y1, d_y1);
    cudaGetSymbolAddress((void**)&h2, d_h2);
    cudaGetSymbolAddress((void**)&y2, d_y2);
    cudaGetSymbolAddress((void**)&es1, d_es1);
    cudaGetSymbolAddress((void**)&ed1, d_ed1);
    cudaGetSymbolAddress((void**)&es2, d_es2);
    cudaGetSymbolAddress((void**)&ed2, d_ed2);
    cudaGetSymbolAddress((void**)&deg, d_deg);
    cudaGetSymbolAddress((void**)&off, d_off);
    cudaGetSymbolAddress((void**)&cursor, d_cursor);
    cudaGetSymbolAddress((void**)&part, d_part);
    cudaGetSymbolAddress((void**)&csrc, d_csrc);
    cudaGetSymbolAddress((void**)&gstart, d_gstart);
    cudaGetSymbolAddress((void**)&bs1, d_bs1);
    cudaGetSymbolAddress((void**)&bq1, d_bq1);
    cudaGetSymbolAddress((void**)&bs2, d_bs2);
    cudaGetSymbolAddress((void**)&bq2, d_bq2);
    cudaGetSymbolAddress((void**)&pooled, d_pooled);
    cudaGetSymbolAddress((void**)&z1, d_z1);
    cudaGetSymbolAddress((void**)&z1n, d_z1n);
    cudaGetSymbolAddress((void**)&z2, d_z2);
    cudaGetSymbolAddress((void**)&z2n, d_z2n);

    const int TB = 256;

    // 1: degree count
    count_deg<<<cdiv(EE, TB), TB>>>(edst, deg);
    // 2-4: parallel scan (was single-block)
    scan_part<<<NB_SCAN, 256>>>(deg, part);
    scan_top<<<1, 256>>>(part);
    scan_write<<<NB_SCAN, 256>>>(deg, part, off, cursor);
    // 5: gemm1 + CSR fill + graph bounds
    combo1<<<GEMM1_BLOCKS + CSR_BLOCKS + 1, 256>>>(x, W1, h1, a_s1, a_d1, es1, ed1,
                                                   esrc, edst, cursor, csrc, batch, gstart);
    // 6: fused GAT layer 1
    fused_gat<128><<<cdiv(NN, 16), 512>>>(off, csrc, es1, ed1, h1, b1, y1, bs1, bq1);
    // 7: gemm2 (BN1 finalize+apply fused)
    gemm_k<<<4 * cdiv(NN, 128), 256>>>(4, y1, W2, h2, NN, 256, 128,
                                       bs1, bq1, g1, be1, a_s2, a_d2, es2, ed2);
    // 8: fused GAT layer 2
    fused_gat<256><<<cdiv(NN, 16), 512>>>(off, csrc, es2, ed2, h2, b2, y2, bs2, bq2);
    // 9: pool (BN2 finalize+relu fused)
    pool_bn<<<GG, 256>>>(y2, gstart, bs2, bq2, g2, be2, pooled);
    // 10-13: FC head
    fc_kernel<<<cdiv(GG * 512, TB), TB>>>(pooled, Wf1, bf1, z1, GG, 512, 256);
    bn_small_relu<<<2, 256>>>(z1, gf1, bef1, z1n, 512);
    fc_kernel<<<cdiv(GG * 256, TB), TB>>>(z1n, Wf2, bf2, z2, GG, 256, 512);
    bn2_final<<<1, 256>>>(z2, gf2, bef2, Wout, bout, z2n, out);
    // 14: tail cleanup for next replay
    cleanup<<<cdiv(NN * 2, TB), TB>>>(deg, es1, ed1, es2, ed2, bs1, bq1, bs2, bq2);
}